// round 5
// baseline (speedup 1.0000x reference)
#include <cuda_runtime.h>
#include <math.h>

// Problem constants
#define BB    8
#define AA    512
#define NBH   64
#define FD    128
#define GD    50
#define NSTR  132
#define PSTR  132
#define FSTR  52

typedef unsigned long long u64;

__device__ __forceinline__ void fma2(u64 &d, u64 a, u64 b) {
    asm("fma.rn.f32x2 %0, %1, %2, %0;" : "+l"(d) : "l"(a), "l"(b));
}
__device__ __forceinline__ u64 pk2(float lo, float hi) {
    u64 r; asm("mov.b64 %0, {%1, %2};" : "=l"(r) : "f"(lo), "f"(hi)); return r;
}
__device__ __forceinline__ float2 upk2(u64 v) {
    float2 t; asm("mov.b64 {%0, %1}, %2;" : "=f"(t.x), "=f"(t.y) : "l"(v)); return t;
}
__device__ __forceinline__ u64 mul2_(u64 a, u64 b) {
    u64 r; asm("mul.rn.f32x2 %0, %1, %2;" : "=l"(r) : "l"(a), "l"(b)); return r;
}
__device__ __forceinline__ u64 add2_(u64 a, u64 b) {
    u64 r; asm("add.rn.f32x2 %0, %1, %2;" : "=l"(r) : "l"(a), "l"(b)); return r;
}

// scratch (device globals: allowed; no allocation)
__device__ float g_p[BB * AA * 1024];   // p[a][h][j]
__device__ float g_u[BB * AA * 1024];   // u[a][h][j]
__device__ int g_mask_u8;

// Detect 1-byte bool vs 4-byte int mask (deterministic).
__global__ void detect_mask_kernel(const unsigned char* __restrict__ m) {
    __shared__ int found;
    if (threadIdx.x == 0) found = 0;
    __syncthreads();
    int acc = 0;
    for (int i = threadIdx.x * 4 + 1; i < 8192; i += blockDim.x * 4)
        if (m[i]) acc = 1;
    if (acc) atomicOr(&found, 1);
    __syncthreads();
    if (threadIdx.x == 0) g_mask_u8 = found;
}

// ---------------------------------------------------------------------------
// K1: p[a][h][j] = sum_d q[a][h*16+d] * Wk[j][h*16+d],  q = x @ Wq
// 16 atoms per block, grid 256. Weights staged in shared 32-row chunks.
// ---------------------------------------------------------------------------
__global__ __launch_bounds__(256)
void k1_kernel(const float* __restrict__ x,
               const float* __restrict__ Wq,
               const float* __restrict__ Wk)
{
    __shared__ __align__(16) float s_x[16 * FD];    // 8 KB
    __shared__ __align__(16) float s_q[16 * FD];    // 8 KB
    __shared__ __align__(16) float s_w[32 * FD];    // 16 KB (chunk stage)

    const int tid = threadIdx.x;
    const int a0  = blockIdx.x * 16;

    ((float4*)s_x)[tid]       = ((const float4*)(x + (size_t)a0 * FD))[tid];
    ((float4*)s_x)[tid + 256] = ((const float4*)(x + (size_t)a0 * FD))[tid + 256];
    __syncthreads();

    // ---- phase 1: q = x_tile @ Wq ----
    const int at = tid >> 4, ft = tid & 15, f0 = ft * 8;
    {
        u64 acc[4] = {0ull, 0ull, 0ull, 0ull};
        for (int k0 = 0; k0 < FD; k0 += 32) {
            __syncthreads();
            #pragma unroll
            for (int i = 0; i < 4; ++i)
                ((float4*)s_w)[tid + 256 * i] =
                    ((const float4*)(Wq + (size_t)k0 * FD))[tid + 256 * i];
            __syncthreads();
            const float* xr = s_x + at * FD + k0;
            #pragma unroll 8
            for (int k = 0; k < 32; ++k) {
                float xv = xr[k];
                u64 x2 = pk2(xv, xv);
                const u64* wr = (const u64*)(s_w + k * FD + f0);
                fma2(acc[0], x2, wr[0]); fma2(acc[1], x2, wr[1]);
                fma2(acc[2], x2, wr[2]); fma2(acc[3], x2, wr[3]);
            }
        }
        ulonglong2 rA, rB;
        rA.x = acc[0]; rA.y = acc[1]; rB.x = acc[2]; rB.y = acc[3];
        *(ulonglong2*)(s_q + at * FD + f0)     = rA;
        *(ulonglong2*)(s_q + at * FD + f0 + 4) = rB;
    }
    __syncthreads();

    // ---- phase 2: p[a][h][j] = dot16(q[a][h*16..], Wk[j][h*16..]) ----
    {
        const int a = tid >> 4, jb = tid & 15;
        for (int j0 = 0; j0 < FD; j0 += 32) {
            __syncthreads();
            #pragma unroll
            for (int i = 0; i < 4; ++i)
                ((float4*)s_w)[tid + 256 * i] =
                    ((const float4*)(Wk + (size_t)j0 * FD))[tid + 256 * i];
            __syncthreads();
            float* pd = g_p + (size_t)(a0 + a) * 1024 + j0;
            #pragma unroll
            for (int h = 0; h < 8; ++h) {
                u64 q2[8];
                const u64* qq = (const u64*)(s_q + a * FD + h * 16);
                #pragma unroll
                for (int d = 0; d < 8; ++d) q2[d] = qq[d];
                #pragma unroll
                for (int jj = 0; jj < 2; ++jj) {
                    const int j = jb + jj * 16;
                    const u64* wr = (const u64*)(s_w + j * FD + h * 16);
                    u64 acc = 0ull;
                    #pragma unroll
                    for (int d = 0; d < 8; ++d) fma2(acc, q2[d], wr[d]);
                    float2 rr = upk2(acc);
                    pd[h * FD + j] = rr.x + rr.y;
                }
            }
        }
    }
}

// ---------------------------------------------------------------------------
// K2: per-atom hot kernel. filter GEMM + gather + scores + softmax + u.
// (unchanged from R4)
// ---------------------------------------------------------------------------
__global__ __launch_bounds__(256, 4)
void k2_kernel(const float* __restrict__ x,
               const float* __restrict__ r_ij,
               const float* __restrict__ f_ij,
               const float* __restrict__ Wf,
               const float* __restrict__ bfilt,
               const int*   __restrict__ nbr,
               const void*  __restrict__ maskp)
{
    __shared__ __align__(16) float s_nbh[NBH * NSTR];  // 33.8 KB
    __shared__ __align__(16) float s_p[8 * PSTR];      // 4.2 KB
    __shared__ __align__(16) float s_un[NBH * FSTR];   // 13.3 KB: fij | sc
    __shared__ float s_C[NBH];
    __shared__ int   s_nb[NBH];
    __shared__ int   s_mk[NBH];

    float* const s_fij = s_un;
    float* const s_sc  = s_un;   // alias: used only after s_fij is dead

    const int tid  = threadIdx.x;
    const int atom = blockIdx.x;
    const int b    = atom >> 9;
    const float* xb  = x + (size_t)b * (AA * FD);
    const size_t an  = (size_t)atom * NBH;
    const int u8 = g_mask_u8;

    // ---- P0: stage p, f_ij (float2), r/nbr/mask ----
    {
        float4 pv = ((const float4*)(g_p + (size_t)atom * 1024))[tid];
        const int i = 4 * tid, h = i >> 7, j = i & 127;
        *(float4*)(s_p + h * PSTR + j) = pv;
    }
    {
        const float2* fsrc = (const float2*)(f_ij + an * GD);
        for (int i = tid; i < NBH * GD / 2; i += 256) {
            int r = i / 25, c2 = i - r * 25;
            *(float2*)(s_fij + r * FSTR + c2 * 2) = fsrc[i];
        }
    }
    if (tid >= 128 && tid < 192) {
        int n = tid - 128;
        float r = r_ij[an + n];
        s_C[n]  = (r < 5.0f) ? 0.5f * (cospif(r * 0.2f) + 1.0f) : 0.0f;
        s_nb[n] = nbr[an + n];
        int mv;
        if (u8) mv = ((const unsigned char*)maskp)[an + n];
        else    mv = ((const int*)maskp)[an + n];
        s_mk[n] = (mv != 0);
    }
    __syncthreads();

    // ---- P2b: filter GEMM (64x128x50) + cutoff + gather -> s_nbh ----
    {
        const int ft = tid & 15, nt = tid >> 4;
        const int f0 = ft * 8, n0 = nt * 4;
        u64 acc[4][4];
        {
            ulonglong2 bA = *(const ulonglong2*)(bfilt + f0);
            ulonglong2 bB = *(const ulonglong2*)(bfilt + f0 + 4);
            #pragma unroll
            for (int i = 0; i < 4; ++i) {
                acc[i][0] = bA.x; acc[i][1] = bA.y;
                acc[i][2] = bB.x; acc[i][3] = bB.y;
            }
        }
        const float* fr = s_fij + n0 * FSTR;
        for (int g = 0; g < GD; g += 2) {
            u64 av[4];
            #pragma unroll
            for (int i = 0; i < 4; ++i) av[i] = *(const u64*)(fr + i * FSTR + g);
            #pragma unroll
            for (int s = 0; s < 2; ++s) {
                const int gg = g + s;
                ulonglong2 wA = *(const ulonglong2*)(Wf + gg * FD + f0);
                ulonglong2 wB = *(const ulonglong2*)(Wf + gg * FD + f0 + 4);
                #pragma unroll
                for (int i = 0; i < 4; ++i) {
                    float2 t = upk2(av[i]);
                    float aval = s ? t.y : t.x;
                    u64 a2 = pk2(aval, aval);
                    fma2(acc[i][0], a2, wA.x);
                    fma2(acc[i][1], a2, wA.y);
                    fma2(acc[i][2], a2, wB.x);
                    fma2(acc[i][3], a2, wB.y);
                }
            }
        }
        #pragma unroll
        for (int i = 0; i < 4; ++i) {
            const int n = n0 + i;
            const float c = s_C[n];
            const u64 c2 = pk2(c, c);
            const float* xg = xb + (size_t)s_nb[n] * FD + f0;
            ulonglong2 gA = *(const ulonglong2*)(xg);
            ulonglong2 gB = *(const ulonglong2*)(xg + 4);
            ulonglong2 rA, rB;
            rA.x = mul2_(mul2_(acc[i][0], gA.x), c2);
            rA.y = mul2_(mul2_(acc[i][1], gA.y), c2);
            rB.x = mul2_(mul2_(acc[i][2], gB.x), c2);
            rB.y = mul2_(mul2_(acc[i][3], gB.y), c2);
            *(ulonglong2*)(s_nbh + n * NSTR + f0)     = rA;
            *(ulonglong2*)(s_nbh + n * NSTR + f0 + 4) = rB;
        }
    }
    __syncthreads();

    // ---- P3: scores[h][n], masked (s_fij now dead -> s_sc alias OK) ----
    {
        const int n = tid & 63, hp = tid >> 6;
        const float* row = s_nbh + n * NSTR;
        const float* pa  = s_p + hp * PSTR;
        const float* pb  = s_p + (hp + 4) * PSTR;
        u64 A0 = 0ull, A1 = 0ull, B0 = 0ull, B1 = 0ull;
        #pragma unroll 4
        for (int j = 0; j < FD; j += 8) {
            ulonglong2 v0 = *(const ulonglong2*)(row + j);
            ulonglong2 v1 = *(const ulonglong2*)(row + j + 4);
            ulonglong2 qa0 = *(const ulonglong2*)(pa + j);
            ulonglong2 qa1 = *(const ulonglong2*)(pa + j + 4);
            ulonglong2 qb0 = *(const ulonglong2*)(pb + j);
            ulonglong2 qb1 = *(const ulonglong2*)(pb + j + 4);
            fma2(A0, v0.x, qa0.x); fma2(A1, v0.y, qa0.y);
            fma2(A0, v1.x, qa1.x); fma2(A1, v1.y, qa1.y);
            fma2(B0, v0.x, qb0.x); fma2(B1, v0.y, qb0.y);
            fma2(B0, v1.x, qb1.x); fma2(B1, v1.y, qb1.y);
        }
        float2 a0 = upk2(A0), a1 = upk2(A1), b0 = upk2(B0), b1 = upk2(B1);
        float sa = (a0.x + a0.y) + (a1.x + a1.y);
        float sb = (b0.x + b0.y) + (b1.x + b1.y);
        const bool m = (s_mk[n] != 0);
        s_sc[hp * 64 + n]       = m ? sa * 0.25f : -1e9f;
        s_sc[(hp + 4) * 64 + n] = m ? sb * 0.25f : -1e9f;
    }
    __syncthreads();

    // ---- P4: softmax, one warp per head ----
    {
        const int h = tid >> 5, lane = tid & 31;
        float* sc = s_sc + h * 64;
        float v0 = sc[lane], v1 = sc[lane + 32];
        float mx = fmaxf(v0, v1);
        #pragma unroll
        for (int o = 16; o > 0; o >>= 1)
            mx = fmaxf(mx, __shfl_xor_sync(0xffffffffu, mx, o));
        float e0 = __expf(v0 - mx), e1 = __expf(v1 - mx);
        float s = e0 + e1;
        #pragma unroll
        for (int o = 16; o > 0; o >>= 1)
            s += __shfl_xor_sync(0xffffffffu, s, o);
        float inv = 1.0f / s;
        sc[lane] = e0 * inv;
        sc[lane + 32] = e1 * inv;
    }
    __syncthreads();

    // ---- P5: u[h][j] -> g_u ----
    {
        const int h = tid >> 5, lane = tid & 31;
        const float* at = s_sc + h * 64;
        u64 a0 = 0ull, a1 = 0ull;
        #pragma unroll 4
        for (int n = 0; n < NBH; ++n) {
            u64 av = pk2(at[n], at[n]);
            ulonglong2 v = *(const ulonglong2*)(s_nbh + n * NSTR + lane * 4);
            fma2(a0, av, v.x);
            fma2(a1, av, v.y);
        }
        ulonglong2 r; r.x = a0; r.y = a1;
        *(ulonglong2*)(g_u + (size_t)atom * 1024 + h * FD + lane * 4) = r;
    }
}

// ---------------------------------------------------------------------------
// K3: msg = blockdiag(u) @ Wv ; out = x + msg @ Wo + bo.
// 16 atoms per block, grid 256. Weights + u staged in shared chunks.
// ---------------------------------------------------------------------------
__global__ __launch_bounds__(256)
void k3_kernel(const float* __restrict__ x,
               const float* __restrict__ Wv,
               const float* __restrict__ Wo,
               const float* __restrict__ bo,
               float*       __restrict__ out)
{
    __shared__ __align__(16) float s_msg[16 * FD];        // 8 KB
    __shared__ __align__(16) float s_w[32 * FD];          // 16 KB
    __shared__ __align__(16) float s_uc[16 * 288];        // 18 KB  [a]*288+[h]*36+j

    const int tid = threadIdx.x;
    const int a0  = blockIdx.x * 16;
    const int at = tid >> 4, ft = tid & 15;
    const int f0 = ft * 8;
    const int h  = f0 >> 4;

    // ---- phase A: msg[a][f] = sum_j u[a][h(f)][j] * Wv[j][f] ----
    {
        u64 acc[4] = {0ull, 0ull, 0ull, 0ull};
        for (int j0 = 0; j0 < FD; j0 += 32) {
            __syncthreads();
            #pragma unroll
            for (int i = 0; i < 4; ++i)
                ((float4*)s_w)[tid + 256 * i] =
                    ((const float4*)(Wv + (size_t)j0 * FD))[tid + 256 * i];
            #pragma unroll
            for (int i = 0; i < 4; ++i) {
                int idx = tid + 256 * i;           // 0..1023 float4s
                int aa = idx >> 6, rem = idx & 63; // rem = hh*8 + jj4
                int hh = rem >> 3, jj4 = rem & 7;
                *(float4*)(s_uc + aa * 288 + hh * 36 + jj4 * 4) =
                    *(const float4*)(g_u + (size_t)(a0 + aa) * 1024 + hh * FD + j0 + jj4 * 4);
            }
            __syncthreads();
            const float* ur = s_uc + at * 288 + h * 36;
            #pragma unroll 8
            for (int j = 0; j < 32; ++j) {
                float uv = ur[j];
                u64 u2 = pk2(uv, uv);
                const u64* wr = (const u64*)(s_w + j * FD + f0);
                fma2(acc[0], u2, wr[0]); fma2(acc[1], u2, wr[1]);
                fma2(acc[2], u2, wr[2]); fma2(acc[3], u2, wr[3]);
            }
        }
        ulonglong2 rA, rB;
        rA.x = acc[0]; rA.y = acc[1]; rB.x = acc[2]; rB.y = acc[3];
        *(ulonglong2*)(s_msg + at * FD + f0)     = rA;
        *(ulonglong2*)(s_msg + at * FD + f0 + 4) = rB;
    }

    // ---- phase B: out[a][f] = x + sum_m msg[a][m]*Wo[m][f] + bo[f] ----
    {
        u64 acc[4];
        {
            ulonglong2 bA = *(const ulonglong2*)(bo + f0);
            ulonglong2 bB = *(const ulonglong2*)(bo + f0 + 4);
            acc[0] = bA.x; acc[1] = bA.y; acc[2] = bB.x; acc[3] = bB.y;
        }
        for (int m0 = 0; m0 < FD; m0 += 32) {
            __syncthreads();
            #pragma unroll
            for (int i = 0; i < 4; ++i)
                ((float4*)s_w)[tid + 256 * i] =
                    ((const float4*)(Wo + (size_t)m0 * FD))[tid + 256 * i];
            __syncthreads();
            const float* mr = s_msg + at * FD + m0;
            #pragma unroll 8
            for (int m = 0; m < 32; ++m) {
                float mv = mr[m];
                u64 m2 = pk2(mv, mv);
                const u64* wr = (const u64*)(s_w + m * FD + f0);
                fma2(acc[0], m2, wr[0]); fma2(acc[1], m2, wr[1]);
                fma2(acc[2], m2, wr[2]); fma2(acc[3], m2, wr[3]);
            }
        }
        const float* xr = x + (size_t)(a0 + at) * FD + f0;
        ulonglong2 x0 = *(const ulonglong2*)(xr);
        ulonglong2 x1 = *(const ulonglong2*)(xr + 4);
        ulonglong2 rA, rB;
        rA.x = add2_(acc[0], x0.x); rA.y = add2_(acc[1], x0.y);
        rB.x = add2_(acc[2], x1.x); rB.y = add2_(acc[3], x1.y);
        *(ulonglong2*)(out + (size_t)(a0 + at) * FD + f0)     = rA;
        *(ulonglong2*)(out + (size_t)(a0 + at) * FD + f0 + 4) = rB;
    }
}

extern "C" void kernel_launch(void* const* d_in, const int* in_sizes, int n_in,
                              void* d_out, int out_size)
{
    // metadata order: e, x, t, r_ij, f_ij, W_filt, b_filt, Wq, Wk, Wv, Wo, bo,
    //                 neighbors, neighbor_mask     (e and t are unused)
    const float* x    = (const float*)d_in[1];
    const float* r    = (const float*)d_in[3];
    const float* fij  = (const float*)d_in[4];
    const float* Wf   = (const float*)d_in[5];
    const float* bf   = (const float*)d_in[6];
    const float* Wq   = (const float*)d_in[7];
    const float* Wk   = (const float*)d_in[8];
    const float* Wv   = (const float*)d_in[9];
    const float* Wo   = (const float*)d_in[10];
    const float* bo   = (const float*)d_in[11];
    const int*   nbr  = (const int*)d_in[12];
    const void*  mk   = d_in[13];

    detect_mask_kernel<<<1, 256>>>((const unsigned char*)mk);
    k1_kernel<<<256, 256>>>(x, Wq, Wk);
    k2_kernel<<<BB * AA, 256>>>(x, r, fij, Wf, bf, nbr, mk);
    k3_kernel<<<256, 256>>>(x, Wv, Wo, bo, (float*)d_out);
}

// round 6
// speedup vs baseline: 1.2421x; 1.2421x over previous
#include <cuda_runtime.h>
#include <math.h>

// Problem constants
#define BB    8
#define AA    512
#define NBH   64
#define FD    128
#define GD    50
// padded shared strides
#define NSTR  132   // s_nbh row stride
#define PSTR  132
#define USTR  136
#define FSTR  52    // s_fij row stride
#define WSTR  402   // s_wf f-block stride (even, conflict-free for stride-402 lanes)

typedef unsigned long long u64;

__device__ __forceinline__ void fma2(u64 &d, u64 a, u64 b) {
    asm("fma.rn.f32x2 %0, %1, %2, %0;" : "+l"(d) : "l"(a), "l"(b));
}
__device__ __forceinline__ u64 pk2(float lo, float hi) {
    u64 r; asm("mov.b64 %0, {%1, %2};" : "=l"(r) : "f"(lo), "f"(hi)); return r;
}
__device__ __forceinline__ float2 upk2(u64 v) {
    float2 t; asm("mov.b64 {%0, %1}, %2;" : "=f"(t.x), "=f"(t.y) : "l"(v)); return t;
}
__device__ __forceinline__ u64 mul2_(u64 a, u64 b) {
    u64 r; asm("mul.rn.f32x2 %0, %1, %2;" : "=l"(r) : "l"(a), "l"(b)); return r;
}

__device__ int g_mask_u8;

// Detect 1-byte bool vs 4-byte int mask (deterministic).
__global__ void detect_mask_kernel(const unsigned char* __restrict__ m) {
    __shared__ int found;
    if (threadIdx.x == 0) found = 0;
    __syncthreads();
    int acc = 0;
    for (int i = threadIdx.x * 4 + 1; i < 8192; i += blockDim.x * 4)
        if (m[i]) acc = 1;
    if (acc) atomicOr(&found, 1);
    __syncthreads();
    if (threadIdx.x == 0) g_mask_u8 = found;
}

__global__ __launch_bounds__(256, 4)
void tdt_kernel(const float* __restrict__ x,
                const float* __restrict__ r_ij,
                const float* __restrict__ f_ij,
                const float* __restrict__ Wf,
                const float* __restrict__ bfilt,
                const float* __restrict__ Wq,
                const float* __restrict__ Wk,
                const float* __restrict__ Wv,
                const float* __restrict__ Wo,
                const float* __restrict__ bo,
                const int*   __restrict__ nbr,
                const void*  __restrict__ maskp,
                float*       __restrict__ out)
{
    __shared__ __align__(16) float s_nbh[NBH * NSTR];   // 33.8 KB  (epoch A: s_wf)
    __shared__ __align__(16) float s_pt[8 * PSTR];      // 4.2 KB   (also P1 partials)
    __shared__ __align__(16) float s_un[NBH * FSTR];    // 13.3 KB  (fij | u/sc/m/part)
    __shared__ __align__(16) float s_q[FD];
    __shared__ __align__(16) float s_xa[FD];
    __shared__ float s_C[NBH];
    __shared__ int   s_nb[NBH];
    __shared__ int   s_mk[NBH];

    float* const s_wf   = s_nbh;                       // epoch A (dead before nbh stores)
    float* const s_fij  = s_un;                        // epoch A
    float* const s_u    = s_un;                        // epoch B
    float* const s_sc   = s_un + 8 * USTR;             // 512 f
    float* const s_m    = s_un + 8 * USTR + 512;       // 128 f
    float* const s_part = s_un + 8 * USTR + 512 + 128; // 256 f

    const int tid  = threadIdx.x;
    const int atom = blockIdx.x;
    const int b    = atom >> 9;
    const float* xb  = x + (size_t)b * (AA * FD);
    const size_t an  = (size_t)atom * NBH;
    const int u8 = g_mask_u8;

    // ---- P0: stage Wf (swizzled), f_ij (float2), x_a, r/nbr/mask ----
    {
        const float2* wsrc = (const float2*)Wf;        // 3200 float2
        for (int i = tid; i < 3200; i += 256) {
            int g = i >> 6, rem = i & 63;              // rem = ft*4 + k2
            int ftb = rem >> 2, k2 = rem & 3;
            *(float2*)(s_wf + ftb * WSTR + g * 8 + k2 * 2) = wsrc[i];
        }
    }
    {
        const float2* fsrc = (const float2*)(f_ij + an * GD);
        for (int i = tid; i < NBH * GD / 2; i += 256) {
            int r = i / 25, c2 = i - r * 25;
            *(float2*)(s_fij + r * FSTR + c2 * 2) = fsrc[i];
        }
    }
    if (tid < FD) s_xa[tid] = x[(size_t)atom * FD + tid];
    if (tid >= 128 && tid < 192) {
        int n = tid - 128;
        float r = r_ij[an + n];
        s_C[n]  = (r < 5.0f) ? 0.5f * (cospif(r * 0.2f) + 1.0f) : 0.0f;
        s_nb[n] = nbr[an + n];
        int mv;
        if (u8) mv = ((const unsigned char*)maskp)[an + n];
        else    mv = ((const int*)maskp)[an + n];
        s_mk[n] = (mv != 0);
    }
    __syncthreads();

    // ---- P1: q = x_a @ Wq  (split-K over 256 threads, partials in s_pt) ----
    {
        const int c = tid & 127, half = tid >> 7;
        const float* wq = Wq + (size_t)(half * 64) * FD + c;
        const float* xs = s_xa + half * 64;
        float a0 = 0.f, a1 = 0.f;
        #pragma unroll 8
        for (int j = 0; j < 64; j += 2) {
            a0 += xs[j]     * wq[j * FD];
            a1 += xs[j + 1] * wq[(j + 1) * FD];
        }
        s_pt[tid] = a0 + a1;
    }
    __syncthreads();
    if (tid < 128) s_q[tid] = s_pt[tid] + s_pt[tid + 128];
    __syncthreads();

    // ---- P2a: p^T[h][j] = sum_d Wk[j][h*16+d]*q[h*16+d] ----
    {
        const int j  = tid >> 1;
        const int hh = (tid & 1) * 4;
        const float* wr = Wk + j * FD + hh * 16;
        #pragma unroll
        for (int hi = 0; hi < 4; ++hi) {
            const int h = hh + hi;
            const u64* wv = (const u64*)(wr + hi * 16);
            const u64* qv = (const u64*)(s_q + h * 16);
            u64 a0 = 0ull, a1 = 0ull;
            #pragma unroll
            for (int p = 0; p < 8; p += 2) {
                fma2(a0, wv[p],     qv[p]);
                fma2(a1, wv[p + 1], qv[p + 1]);
            }
            float2 r0 = upk2(a0), r1 = upk2(a1);
            s_pt[h * PSTR + j] = (r0.x + r0.y) + (r1.x + r1.y);
        }
    }

    // ---- P2b: filter GEMM (64x128x50), Wf from shared ----
    {
        const int ft = tid & 15, nt = tid >> 4;
        const int f0 = ft * 8, n0 = nt * 4;
        u64 acc[4][4];
        {
            ulonglong2 bA = *(const ulonglong2*)(bfilt + f0);
            ulonglong2 bB = *(const ulonglong2*)(bfilt + f0 + 4);
            #pragma unroll
            for (int i = 0; i < 4; ++i) {
                acc[i][0] = bA.x; acc[i][1] = bA.y;
                acc[i][2] = bB.x; acc[i][3] = bB.y;
            }
        }
        const float* fr = s_fij + n0 * FSTR;
        const float* wbase = s_wf + ft * WSTR;
        for (int g = 0; g < GD; g += 2) {
            u64 av[4];
            #pragma unroll
            for (int i = 0; i < 4; ++i) av[i] = *(const u64*)(fr + i * FSTR + g);
            #pragma unroll
            for (int s = 0; s < 2; ++s) {
                const u64* wr = (const u64*)(wbase + (g + s) * 8);
                u64 w0 = wr[0], w1 = wr[1], w2 = wr[2], w3 = wr[3];
                #pragma unroll
                for (int i = 0; i < 4; ++i) {
                    float2 t = upk2(av[i]);
                    float aval = s ? t.y : t.x;
                    u64 a2 = pk2(aval, aval);
                    fma2(acc[i][0], a2, w0);
                    fma2(acc[i][1], a2, w1);
                    fma2(acc[i][2], a2, w2);
                    fma2(acc[i][3], a2, w3);
                }
            }
        }
        __syncthreads();   // all s_wf reads done before s_nbh stores (alias)
        #pragma unroll
        for (int i = 0; i < 4; ++i) {
            const int n = n0 + i;
            const float c = s_C[n];
            const u64 c2 = pk2(c, c);
            const float* xg = xb + (size_t)s_nb[n] * FD + f0;
            ulonglong2 gA = *(const ulonglong2*)(xg);
            ulonglong2 gB = *(const ulonglong2*)(xg + 4);
            ulonglong2 rA, rB;
            rA.x = mul2_(mul2_(acc[i][0], gA.x), c2);
            rA.y = mul2_(mul2_(acc[i][1], gA.y), c2);
            rB.x = mul2_(mul2_(acc[i][2], gB.x), c2);
            rB.y = mul2_(mul2_(acc[i][3], gB.y), c2);
            *(ulonglong2*)(s_nbh + n * NSTR + f0)     = rA;
            *(ulonglong2*)(s_nbh + n * NSTR + f0 + 4) = rB;
        }
    }
    __syncthreads();

    // ---- P3: scores[h][n], masked (s_fij dead -> s_sc alias OK) ----
    {
        const int n = tid & 63, hp = tid >> 6;
        const float* row = s_nbh + n * NSTR;
        const float* pa  = s_pt + hp * PSTR;
        const float* pb  = s_pt + (hp + 4) * PSTR;
        u64 A0 = 0ull, A1 = 0ull, B0 = 0ull, B1 = 0ull;
        #pragma unroll 4
        for (int j = 0; j < FD; j += 8) {
            ulonglong2 v0 = *(const ulonglong2*)(row + j);
            ulonglong2 v1 = *(const ulonglong2*)(row + j + 4);
            ulonglong2 qa0 = *(const ulonglong2*)(pa + j);
            ulonglong2 qa1 = *(const ulonglong2*)(pa + j + 4);
            ulonglong2 qb0 = *(const ulonglong2*)(pb + j);
            ulonglong2 qb1 = *(const ulonglong2*)(pb + j + 4);
            fma2(A0, v0.x, qa0.x); fma2(A1, v0.y, qa0.y);
            fma2(A0, v1.x, qa1.x); fma2(A1, v1.y, qa1.y);
            fma2(B0, v0.x, qb0.x); fma2(B1, v0.y, qb0.y);
            fma2(B0, v1.x, qb1.x); fma2(B1, v1.y, qb1.y);
        }
        float2 a0 = upk2(A0), a1 = upk2(A1), b0 = upk2(B0), b1 = upk2(B1);
        float sa = (a0.x + a0.y) + (a1.x + a1.y);
        float sb = (b0.x + b0.y) + (b1.x + b1.y);
        const bool m = (s_mk[n] != 0);
        s_sc[hp * 64 + n]       = m ? sa * 0.25f : -1e9f;
        s_sc[(hp + 4) * 64 + n] = m ? sb * 0.25f : -1e9f;
    }
    __syncthreads();

    // ---- P4: softmax, one warp per head ----
    {
        const int h = tid >> 5, lane = tid & 31;
        float* sc = s_sc + h * 64;
        float v0 = sc[lane], v1 = sc[lane + 32];
        float mx = fmaxf(v0, v1);
        #pragma unroll
        for (int o = 16; o > 0; o >>= 1)
            mx = fmaxf(mx, __shfl_xor_sync(0xffffffffu, mx, o));
        float e0 = __expf(v0 - mx), e1 = __expf(v1 - mx);
        float s = e0 + e1;
        #pragma unroll
        for (int o = 16; o > 0; o >>= 1)
            s += __shfl_xor_sync(0xffffffffu, s, o);
        float inv = 1.0f / s;
        sc[lane] = e0 * inv;
        sc[lane + 32] = e1 * inv;
    }
    __syncthreads();

    // ---- P5: u[h][j] = sum_n attn[h][n]*nbh[n][j] ----
    {
        const int h = tid >> 5, lane = tid & 31;
        const float* at = s_sc + h * 64;
        u64 a0 = 0ull, a1 = 0ull;
        #pragma unroll 4
        for (int n = 0; n < NBH; ++n) {
            u64 av = pk2(at[n], at[n]);
            ulonglong2 v = *(const ulonglong2*)(s_nbh + n * NSTR + lane * 4);
            fma2(a0, av, v.x);
            fma2(a1, av, v.y);
        }
        ulonglong2 r; r.x = a0; r.y = a1;
        *(ulonglong2*)(s_u + h * USTR + lane * 4) = r;
    }
    __syncthreads();

    // ---- P6: msg[f] = sum_j u[h(f)][j]*Wv[j][f]  (split-K, 256 threads) ----
    {
        const int c = tid & 127, half = tid >> 7;
        const int h = c >> 4;
        const float* u  = s_u + h * USTR + half * 64;
        const float* wv = Wv + (size_t)(half * 64) * FD + c;
        float a0 = 0.f, a1 = 0.f;
        #pragma unroll 8
        for (int j = 0; j < 64; j += 2) {
            a0 += u[j]     * wv[j * FD];
            a1 += u[j + 1] * wv[(j + 1) * FD];
        }
        s_part[tid] = a0 + a1;
    }
    __syncthreads();
    if (tid < 128) s_m[tid] = s_part[tid] + s_part[tid + 128];
    __syncthreads();

    // ---- P7: out[f] = x[f] + bo[f] + sum_j msg[j]*Wo[j][f]  (split-K) ----
    {
        const int c = tid & 127, half = tid >> 7;
        const float* mm = s_m + half * 64;
        const float* wo = Wo + (size_t)(half * 64) * FD + c;
        float a0 = half ? 0.f : bo[c], a1 = 0.f;
        #pragma unroll 8
        for (int j = 0; j < 64; j += 2) {
            a0 += mm[j]     * wo[j * FD];
            a1 += mm[j + 1] * wo[(j + 1) * FD];
        }
        s_part[tid] = a0 + a1;
    }
    __syncthreads();
    if (tid < 128)
        out[(size_t)atom * FD + tid] = s_xa[tid] + s_part[tid] + s_part[tid + 128];
}

extern "C" void kernel_launch(void* const* d_in, const int* in_sizes, int n_in,
                              void* d_out, int out_size)
{
    // metadata order: e, x, t, r_ij, f_ij, W_filt, b_filt, Wq, Wk, Wv, Wo, bo,
    //                 neighbors, neighbor_mask     (e and t are unused)
    const float* x    = (const float*)d_in[1];
    const float* r    = (const float*)d_in[3];
    const float* fij  = (const float*)d_in[4];
    const float* Wf   = (const float*)d_in[5];
    const float* bf   = (const float*)d_in[6];
    const float* Wq   = (const float*)d_in[7];
    const float* Wk   = (const float*)d_in[8];
    const float* Wv   = (const float*)d_in[9];
    const float* Wo   = (const float*)d_in[10];
    const float* bo   = (const float*)d_in[11];
    const int*   nbr  = (const int*)d_in[12];
    const void*  mk   = d_in[13];

    detect_mask_kernel<<<1, 256>>>((const unsigned char*)mk);
    tdt_kernel<<<BB * AA, 256>>>(x, r, fij, Wf, bf, Wq, Wk, Wv, Wo, bo,
                                 nbr, mk, (float*)d_out);
}

// round 7
// speedup vs baseline: 1.9535x; 1.5728x over previous
#include <cuda_runtime.h>
#include <math.h>

// Problem constants
#define BB    8
#define AA    512
#define NBH   64
#define FD    128
#define GD    50
// padded shared strides
#define NSTR  132   // s_nbh row stride
#define PSTR  132
#define USTR  136
#define FSTR  52    // s_fij row stride
#define WSTR  402   // s_wf f-block stride (18*ft mod 32 distinct -> conflict-free)

typedef unsigned long long u64;

__device__ __forceinline__ void fma2(u64 &d, u64 a, u64 b) {
    asm("fma.rn.f32x2 %0, %1, %2, %0;" : "+l"(d) : "l"(a), "l"(b));
}
__device__ __forceinline__ u64 pk2(float lo, float hi) {
    u64 r; asm("mov.b64 %0, {%1, %2};" : "=l"(r) : "f"(lo), "f"(hi)); return r;
}
__device__ __forceinline__ float2 upk2(u64 v) {
    float2 t; asm("mov.b64 {%0, %1}, %2;" : "=f"(t.x), "=f"(t.y) : "l"(v)); return t;
}
__device__ __forceinline__ u64 mul2_(u64 a, u64 b) {
    u64 r; asm("mul.rn.f32x2 %0, %1, %2;" : "=l"(r) : "l"(a), "l"(b)); return r;
}

__device__ int g_mask_u8;

// Detect 1-byte bool vs 4-byte int mask (deterministic).
__global__ void detect_mask_kernel(const unsigned char* __restrict__ m) {
    __shared__ int found;
    if (threadIdx.x == 0) found = 0;
    __syncthreads();
    int acc = 0;
    for (int i = threadIdx.x * 4 + 1; i < 8192; i += blockDim.x * 4)
        if (m[i]) acc = 1;
    if (acc) atomicOr(&found, 1);
    __syncthreads();
    if (threadIdx.x == 0) g_mask_u8 = found;
}

__global__ __launch_bounds__(256, 4)
void tdt_kernel(const float* __restrict__ x,
                const float* __restrict__ r_ij,
                const float* __restrict__ f_ij,
                const float* __restrict__ Wf,
                const float* __restrict__ bfilt,
                const float* __restrict__ Wq,
                const float* __restrict__ Wk,
                const float* __restrict__ Wv,
                const float* __restrict__ Wo,
                const float* __restrict__ bo,
                const int*   __restrict__ nbr,
                const void*  __restrict__ maskp,
                float*       __restrict__ out)
{
    __shared__ __align__(16) float s_nbh[NBH * NSTR];   // 33.8 KB  (epoch A: s_wf)
    __shared__ __align__(16) float s_pt[8 * PSTR];      // 4.2 KB   (also P1 partials)
    __shared__ __align__(16) float s_un[NBH * FSTR];    // 13.3 KB  (fij | u/sc/scT/m/part)
    __shared__ __align__(16) float s_q[FD];
    __shared__ __align__(16) float s_xa[FD];
    __shared__ float s_C[NBH];
    __shared__ int   s_nb[NBH];
    __shared__ int   s_mk[NBH];

    float* const s_wf   = s_nbh;                        // epoch A
    float* const s_fij  = s_un;                         // epoch A
    float* const s_u    = s_un;                         // epoch B: 1088 f
    float* const s_sc   = s_un + 8 * USTR;              // 512 f  [h][n]
    float* const s_scT  = s_un + 8 * USTR + 512;        // 512 f  [n][h]
    float* const s_m    = s_un + 8 * USTR + 1024;       // 128 f
    float* const s_part = s_un + 8 * USTR + 1024 + 128; // 256 f

    const int tid  = threadIdx.x;
    const int atom = blockIdx.x;
    const int b    = atom >> 9;
    const float* xb  = x + (size_t)b * (AA * FD);
    const size_t an  = (size_t)atom * NBH;
    const int u8 = g_mask_u8;

    // ---- P0: stage Wf (swizzled), f_ij (float2), x_a, r/nbr/mask ----
    {
        const float2* wsrc = (const float2*)Wf;        // 3200 float2
        for (int i = tid; i < 3200; i += 256) {
            int g = i >> 6, rem = i & 63;              // rem = ft*4 + k2
            int ftb = rem >> 2, k2 = rem & 3;
            *(float2*)(s_wf + ftb * WSTR + g * 8 + k2 * 2) = wsrc[i];
        }
    }
    {
        const float2* fsrc = (const float2*)(f_ij + an * GD);
        for (int i = tid; i < NBH * GD / 2; i += 256) {
            int r = i / 25, c2 = i - r * 25;
            *(float2*)(s_fij + r * FSTR + c2 * 2) = fsrc[i];
        }
    }
    if (tid < FD) s_xa[tid] = x[(size_t)atom * FD + tid];
    if (tid >= 128 && tid < 192) {
        int n = tid - 128;
        float r = r_ij[an + n];
        s_C[n]  = (r < 5.0f) ? 0.5f * (cospif(r * 0.2f) + 1.0f) : 0.0f;
        s_nb[n] = nbr[an + n];
        int mv;
        if (u8) mv = ((const unsigned char*)maskp)[an + n];
        else    mv = ((const int*)maskp)[an + n];
        s_mk[n] = (mv != 0);
    }
    __syncthreads();

    // ---- P1: q = x_a @ Wq  (split-K over 256 threads, partials in s_pt) ----
    {
        const int c = tid & 127, half = tid >> 7;
        const float* wq = Wq + (size_t)(half * 64) * FD + c;
        const float* xs = s_xa + half * 64;
        float a0 = 0.f, a1 = 0.f;
        #pragma unroll 8
        for (int j = 0; j < 64; j += 2) {
            a0 += xs[j]     * wq[j * FD];
            a1 += xs[j + 1] * wq[(j + 1) * FD];
        }
        s_pt[tid] = a0 + a1;
    }
    __syncthreads();
    if (tid < 128) s_q[tid] = s_pt[tid] + s_pt[tid + 128];
    __syncthreads();

    // ---- P2a: p^T[h][j] = sum_d Wk[j][h*16+d]*q[h*16+d]
    //      Fully coalesced: each warp-instr reads one full 512B Wk row. ----
    {
        const int w = tid >> 5, k = tid & 31;      // k = 16B chunk index
        const int h = k >> 2;
        const float4 qc = *(const float4*)(s_q + 4 * k);
        #pragma unroll 4
        for (int jj = 0; jj < 16; ++jj) {
            const int j = w * 16 + jj;
            float4 wv = *(const float4*)(Wk + j * FD + 4 * k);
            float d = wv.x * qc.x + wv.y * qc.y + wv.z * qc.z + wv.w * qc.w;
            d += __shfl_xor_sync(0xffffffffu, d, 1);
            d += __shfl_xor_sync(0xffffffffu, d, 2);
            if ((k & 3) == 0) s_pt[h * PSTR + j] = d;
        }
    }

    // ---- P2b: filter GEMM (64x128x50), Wf from shared ----
    {
        const int ft = tid & 15, nt = tid >> 4;
        const int f0 = ft * 8, n0 = nt * 4;
        u64 acc[4][4];
        {
            ulonglong2 bA = *(const ulonglong2*)(bfilt + f0);
            ulonglong2 bB = *(const ulonglong2*)(bfilt + f0 + 4);
            #pragma unroll
            for (int i = 0; i < 4; ++i) {
                acc[i][0] = bA.x; acc[i][1] = bA.y;
                acc[i][2] = bB.x; acc[i][3] = bB.y;
            }
        }
        const float* fr = s_fij + n0 * FSTR;
        const float* wbase = s_wf + ft * WSTR;
        for (int g = 0; g < GD; g += 2) {
            u64 av[4];
            #pragma unroll
            for (int i = 0; i < 4; ++i) av[i] = *(const u64*)(fr + i * FSTR + g);
            #pragma unroll
            for (int s = 0; s < 2; ++s) {
                const u64* wr = (const u64*)(wbase + (g + s) * 8);
                u64 w0 = wr[0], w1 = wr[1], w2 = wr[2], w3 = wr[3];
                #pragma unroll
                for (int i = 0; i < 4; ++i) {
                    float2 t = upk2(av[i]);
                    float aval = s ? t.y : t.x;
                    u64 a2 = pk2(aval, aval);
                    fma2(acc[i][0], a2, w0);
                    fma2(acc[i][1], a2, w1);
                    fma2(acc[i][2], a2, w2);
                    fma2(acc[i][3], a2, w3);
                }
            }
        }
        __syncthreads();   // all s_wf reads done before s_nbh stores (alias)
        #pragma unroll
        for (int i = 0; i < 4; ++i) {
            const int n = n0 + i;
            const float c = s_C[n];
            const u64 c2 = pk2(c, c);
            const float* xg = xb + (size_t)s_nb[n] * FD + f0;
            ulonglong2 gA = *(const ulonglong2*)(xg);
            ulonglong2 gB = *(const ulonglong2*)(xg + 4);
            ulonglong2 rA, rB;
            rA.x = mul2_(mul2_(acc[i][0], gA.x), c2);
            rA.y = mul2_(mul2_(acc[i][1], gA.y), c2);
            rB.x = mul2_(mul2_(acc[i][2], gB.x), c2);
            rB.y = mul2_(mul2_(acc[i][3], gB.y), c2);
            *(ulonglong2*)(s_nbh + n * NSTR + f0)     = rA;
            *(ulonglong2*)(s_nbh + n * NSTR + f0 + 4) = rB;
        }
    }
    __syncthreads();

    // ---- P3: scores[h][n], masked (s_fij dead -> s_sc alias OK) ----
    {
        const int n = tid & 63, hp = tid >> 6;
        const float* row = s_nbh + n * NSTR;
        const float* pa  = s_pt + hp * PSTR;
        const float* pb  = s_pt + (hp + 4) * PSTR;
        u64 A0 = 0ull, A1 = 0ull, B0 = 0ull, B1 = 0ull;
        #pragma unroll 4
        for (int j = 0; j < FD; j += 8) {
            ulonglong2 v0 = *(const ulonglong2*)(row + j);
            ulonglong2 v1 = *(const ulonglong2*)(row + j + 4);
            ulonglong2 qa0 = *(const ulonglong2*)(pa + j);
            ulonglong2 qa1 = *(const ulonglong2*)(pa + j + 4);
            ulonglong2 qb0 = *(const ulonglong2*)(pb + j);
            ulonglong2 qb1 = *(const ulonglong2*)(pb + j + 4);
            fma2(A0, v0.x, qa0.x); fma2(A1, v0.y, qa0.y);
            fma2(A0, v1.x, qa1.x); fma2(A1, v1.y, qa1.y);
            fma2(B0, v0.x, qb0.x); fma2(B1, v0.y, qb0.y);
            fma2(B0, v1.x, qb1.x); fma2(B1, v1.y, qb1.y);
        }
        float2 a0 = upk2(A0), a1 = upk2(A1), b0 = upk2(B0), b1 = upk2(B1);
        float sa = (a0.x + a0.y) + (a1.x + a1.y);
        float sb = (b0.x + b0.y) + (b1.x + b1.y);
        const bool m = (s_mk[n] != 0);
        s_sc[hp * 64 + n]       = m ? sa * 0.25f : -1e9f;
        s_sc[(hp + 4) * 64 + n] = m ? sb * 0.25f : -1e9f;
    }
    __syncthreads();

    // ---- P4: softmax, one warp per head; write attn TRANSPOSED [n][h] ----
    {
        const int h = tid >> 5, lane = tid & 31;
        const float* sc = s_sc + h * 64;
        float v0 = sc[lane], v1 = sc[lane + 32];
        float mx = fmaxf(v0, v1);
        #pragma unroll
        for (int o = 16; o > 0; o >>= 1)
            mx = fmaxf(mx, __shfl_xor_sync(0xffffffffu, mx, o));
        float e0 = __expf(v0 - mx), e1 = __expf(v1 - mx);
        float s = e0 + e1;
        #pragma unroll
        for (int o = 16; o > 0; o >>= 1)
            s += __shfl_xor_sync(0xffffffffu, s, o);
        float inv = 1.0f / s;
        s_scT[lane * 8 + h]        = e0 * inv;
        s_scT[(lane + 32) * 8 + h] = e1 * inv;
    }
    __syncthreads();

    // ---- P5: u[h][j] = sum_n attn[n][h]*nbh[n][j], column-owned (tile read 1x) ----
    {
        const int w = tid >> 5, lane = tid & 31;
        const int half = lane >> 4, cc = lane & 15;
        const int col = w * 16 + cc;
        const int nbase = half * 32;
        u64 acc[4] = {0ull, 0ull, 0ull, 0ull};
        #pragma unroll 4
        for (int i = 0; i < 32; ++i) {
            const int n = nbase + i;
            float v = s_nbh[n * NSTR + col];
            u64 v2 = pk2(v, v);
            const u64* at2 = (const u64*)(s_scT + n * 8);
            fma2(acc[0], v2, at2[0]);
            fma2(acc[1], v2, at2[1]);
            fma2(acc[2], v2, at2[2]);
            fma2(acc[3], v2, at2[3]);
        }
        #pragma unroll
        for (int t = 0; t < 4; ++t) {
            float2 p = upk2(acc[t]);
            p.x += __shfl_xor_sync(0xffffffffu, p.x, 16);
            p.y += __shfl_xor_sync(0xffffffffu, p.y, 16);
            if (half == 0) {
                s_u[(2 * t) * USTR + col]     = p.x;
                s_u[(2 * t + 1) * USTR + col] = p.y;
            }
        }
    }
    __syncthreads();

    // ---- P6: msg[f] = sum_j u[h(f)][j]*Wv[j][f]  (split-K, 256 threads) ----
    {
        const int c = tid & 127, half = tid >> 7;
        const int h = c >> 4;
        const float* u  = s_u + h * USTR + half * 64;
        const float* wv = Wv + (size_t)(half * 64) * FD + c;
        float a0 = 0.f, a1 = 0.f;
        #pragma unroll 8
        for (int j = 0; j < 64; j += 2) {
            a0 += u[j]     * wv[j * FD];
            a1 += u[j + 1] * wv[(j + 1) * FD];
        }
        s_part[tid] = a0 + a1;
    }
    __syncthreads();
    if (tid < 128) s_m[tid] = s_part[tid] + s_part[tid + 128];
    __syncthreads();

    // ---- P7: out[f] = x[f] + bo[f] + sum_j msg[j]*Wo[j][f]  (split-K) ----
    {
        const int c = tid & 127, half = tid >> 7;
        const float* mm = s_m + half * 64;
        const float* wo = Wo + (size_t)(half * 64) * FD + c;
        float a0 = half ? 0.f : bo[c], a1 = 0.f;
        #pragma unroll 8
        for (int j = 0; j < 64; j += 2) {
            a0 += mm[j]     * wo[j * FD];
            a1 += mm[j + 1] * wo[(j + 1) * FD];
        }
        s_part[tid] = a0 + a1;
    }
    __syncthreads();
    if (tid < 128)
        out[(size_t)atom * FD + tid] = s_xa[tid] + s_part[tid] + s_part[tid + 128];
}

extern "C" void kernel_launch(void* const* d_in, const int* in_sizes, int n_in,
                              void* d_out, int out_size)
{
    // metadata order: e, x, t, r_ij, f_ij, W_filt, b_filt, Wq, Wk, Wv, Wo, bo,
    //                 neighbors, neighbor_mask     (e and t are unused)
    const float* x    = (const float*)d_in[1];
    const float* r    = (const float*)d_in[3];
    const float* fij  = (const float*)d_in[4];
    const float* Wf   = (const float*)d_in[5];
    const float* bf   = (const float*)d_in[6];
    const float* Wq   = (const float*)d_in[7];
    const float* Wk   = (const float*)d_in[8];
    const float* Wv   = (const float*)d_in[9];
    const float* Wo   = (const float*)d_in[10];
    const float* bo   = (const float*)d_in[11];
    const int*   nbr  = (const int*)d_in[12];
    const void*  mk   = d_in[13];

    detect_mask_kernel<<<1, 256>>>((const unsigned char*)mk);
    tdt_kernel<<<BB * AA, 256>>>(x, r, fij, Wf, bf, Wq, Wk, Wv, Wo, bo,
                                 nbr, mk, (float*)d_out);
}

// round 8
// speedup vs baseline: 1.9900x; 1.0187x over previous
#include <cuda_runtime.h>
#include <math.h>

// Problem constants
#define BB    8
#define AA    512
#define NBH   64
#define FD    128
#define GD    50
// padded shared strides
#define NSTR  132   // s_nbh row stride
#define PSTR  132
#define USTR  136
#define FSTR  52    // s_fij row stride
#define WSTR  402   // s_wf f-block stride

typedef unsigned long long u64;

__device__ __forceinline__ void fma2(u64 &d, u64 a, u64 b) {
    asm("fma.rn.f32x2 %0, %1, %2, %0;" : "+l"(d) : "l"(a), "l"(b));
}
__device__ __forceinline__ u64 pk2(float lo, float hi) {
    u64 r; asm("mov.b64 %0, {%1, %2};" : "=l"(r) : "f"(lo), "f"(hi)); return r;
}
__device__ __forceinline__ float2 upk2(u64 v) {
    float2 t; asm("mov.b64 {%0, %1}, %2;" : "=f"(t.x), "=f"(t.y) : "l"(v)); return t;
}
__device__ __forceinline__ u64 mul2_(u64 a, u64 b) {
    u64 r; asm("mul.rn.f32x2 %0, %1, %2;" : "=l"(r) : "l"(a), "l"(b)); return r;
}
__device__ __forceinline__ u64 add2_(u64 a, u64 b) {
    u64 r; asm("add.rn.f32x2 %0, %1, %2;" : "=l"(r) : "l"(a), "l"(b)); return r;
}

__device__ int g_mask_u8;

// Detect 1-byte bool vs 4-byte int mask (deterministic).
__global__ void detect_mask_kernel(const unsigned char* __restrict__ m) {
    __shared__ int found;
    if (threadIdx.x == 0) found = 0;
    __syncthreads();
    int acc = 0;
    for (int i = threadIdx.x * 4 + 1; i < 8192; i += blockDim.x * 4)
        if (m[i]) acc = 1;
    if (acc) atomicOr(&found, 1);
    __syncthreads();
    if (threadIdx.x == 0) g_mask_u8 = found;
}

__global__ __launch_bounds__(256, 4)
void tdt_kernel(const float* __restrict__ x,
                const float* __restrict__ r_ij,
                const float* __restrict__ f_ij,
                const float* __restrict__ Wf,
                const float* __restrict__ bfilt,
                const float* __restrict__ Wq,
                const float* __restrict__ Wk,
                const float* __restrict__ Wv,
                const float* __restrict__ Wo,
                const float* __restrict__ bo,
                const int*   __restrict__ nbr,
                const void*  __restrict__ maskp,
                float*       __restrict__ out)
{
    __shared__ __align__(16) float s_nbh[NBH * NSTR];   // 33.8 KB  (epoch A: s_wf)
    __shared__ __align__(16) float s_pt[8 * PSTR];      // 4.2 KB   (P1 partials | p^T [j][h])
    __shared__ __align__(16) float s_un[NBH * FSTR];    // 13.3 KB  multi-epoch
    __shared__ __align__(16) float s_q[FD];
    __shared__ __align__(16) float s_xa[FD];
    __shared__ float s_C[NBH];
    __shared__ int   s_nb[NBH];
    __shared__ int   s_mk[NBH];

    // s_un epochs (all ranges in floats, verified disjoint per phase):
    //   A (P0-P2b): s_fij [0, 3328)
    //   P3:  s_red  [0, 2112)  (u64 view, stride-66 padded)
    //   P3r: s_sc   [2112, 2624)
    //   P4:  s_scT  [2624, 3136)
    //   P5:  s_u    [384, 1472)
    //   P6/P7: s_m [0,128), s_part [128, 384)
    float* const s_fij  = s_un;
    float* const s_u    = s_un + 384;
    float* const s_sc   = s_un + 2112;
    float* const s_scT  = s_un + 2624;
    float* const s_m    = s_un;
    float* const s_part = s_un + 128;
    float* const s_wf   = s_nbh;                        // epoch A

    const int tid  = threadIdx.x;
    const int atom = blockIdx.x;
    const int b    = atom >> 9;
    const float* xb  = x + (size_t)b * (AA * FD);
    const size_t an  = (size_t)atom * NBH;
    const int u8 = g_mask_u8;

    // ---- P0: stage Wf (swizzled), f_ij (float2), x_a, r/nbr/mask ----
    {
        const float2* wsrc = (const float2*)Wf;        // 3200 float2
        for (int i = tid; i < 3200; i += 256) {
            int g = i >> 6, rem = i & 63;              // rem = ft*4 + k2
            int ftb = rem >> 2, k2 = rem & 3;
            *(float2*)(s_wf + ftb * WSTR + g * 8 + k2 * 2) = wsrc[i];
        }
    }
    {
        const float2* fsrc = (const float2*)(f_ij + an * GD);
        for (int i = tid; i < NBH * GD / 2; i += 256) {
            int r = i / 25, c2 = i - r * 25;
            *(float2*)(s_fij + r * FSTR + c2 * 2) = fsrc[i];
        }
    }
    if (tid < FD) s_xa[tid] = x[(size_t)atom * FD + tid];
    if (tid >= 128 && tid < 192) {
        int n = tid - 128;
        float r = r_ij[an + n];
        s_C[n]  = (r < 5.0f) ? 0.5f * (cospif(r * 0.2f) + 1.0f) : 0.0f;
        s_nb[n] = nbr[an + n];
        int mv;
        if (u8) mv = ((const unsigned char*)maskp)[an + n];
        else    mv = ((const int*)maskp)[an + n];
        s_mk[n] = (mv != 0);
    }
    __syncthreads();

    // ---- P1: q = x_a @ Wq  (split-K over 256 threads, partials in s_pt) ----
    {
        const int c = tid & 127, half = tid >> 7;
        const float* wq = Wq + (size_t)(half * 64) * FD + c;
        const float* xs = s_xa + half * 64;
        float a0 = 0.f, a1 = 0.f;
        #pragma unroll 8
        for (int j = 0; j < 64; j += 2) {
            a0 += xs[j]     * wq[j * FD];
            a1 += xs[j + 1] * wq[(j + 1) * FD];
        }
        s_pt[tid] = a0 + a1;
    }
    __syncthreads();
    if (tid < 128) s_q[tid] = s_pt[tid] + s_pt[tid + 128];
    __syncthreads();

    // ---- P2a: p^T[j][h] = sum_d Wk[j][h*16+d]*q[h*16+d]
    //      Fully coalesced full-row reads; TRANSPOSED store [j][h]. ----
    {
        const int w = tid >> 5, k = tid & 31;      // k = 16B chunk index
        const int h = k >> 2;
        const float4 qc = *(const float4*)(s_q + 4 * k);
        #pragma unroll 4
        for (int jj = 0; jj < 16; ++jj) {
            const int j = w * 16 + jj;
            float4 wv = *(const float4*)(Wk + j * FD + 4 * k);
            float d = wv.x * qc.x + wv.y * qc.y + wv.z * qc.z + wv.w * qc.w;
            d += __shfl_xor_sync(0xffffffffu, d, 1);
            d += __shfl_xor_sync(0xffffffffu, d, 2);
            if ((k & 3) == 0) s_pt[j * 8 + h] = d;
        }
    }

    // ---- P2b: filter GEMM (64x128x50), Wf from shared ----
    {
        const int ft = tid & 15, nt = tid >> 4;
        const int f0 = ft * 8, n0 = nt * 4;
        u64 acc[4][4];
        {
            ulonglong2 bA = *(const ulonglong2*)(bfilt + f0);
            ulonglong2 bB = *(const ulonglong2*)(bfilt + f0 + 4);
            #pragma unroll
            for (int i = 0; i < 4; ++i) {
                acc[i][0] = bA.x; acc[i][1] = bA.y;
                acc[i][2] = bB.x; acc[i][3] = bB.y;
            }
        }
        const float* fr = s_fij + n0 * FSTR;
        const float* wbase = s_wf + ft * WSTR;
        for (int g = 0; g < GD; g += 2) {
            u64 av[4];
            #pragma unroll
            for (int i = 0; i < 4; ++i) av[i] = *(const u64*)(fr + i * FSTR + g);
            #pragma unroll
            for (int s = 0; s < 2; ++s) {
                const u64* wr = (const u64*)(wbase + (g + s) * 8);
                u64 w0 = wr[0], w1 = wr[1], w2 = wr[2], w3 = wr[3];
                #pragma unroll
                for (int i = 0; i < 4; ++i) {
                    float2 t = upk2(av[i]);
                    float aval = s ? t.y : t.x;
                    u64 a2 = pk2(aval, aval);
                    fma2(acc[i][0], a2, w0);
                    fma2(acc[i][1], a2, w1);
                    fma2(acc[i][2], a2, w2);
                    fma2(acc[i][3], a2, w3);
                }
            }
        }
        __syncthreads();   // all s_wf reads done before s_nbh stores (alias)
        #pragma unroll
        for (int i = 0; i < 4; ++i) {
            const int n = n0 + i;
            const float c = s_C[n];
            const u64 c2 = pk2(c, c);
            const float* xg = xb + (size_t)s_nb[n] * FD + f0;
            ulonglong2 gA = *(const ulonglong2*)(xg);
            ulonglong2 gB = *(const ulonglong2*)(xg + 4);
            ulonglong2 rA, rB;
            rA.x = mul2_(mul2_(acc[i][0], gA.x), c2);
            rA.y = mul2_(mul2_(acc[i][1], gA.y), c2);
            rB.x = mul2_(mul2_(acc[i][2], gB.x), c2);
            rB.y = mul2_(mul2_(acc[i][3], gB.y), c2);
            *(ulonglong2*)(s_nbh + n * NSTR + f0)     = rA;
            *(ulonglong2*)(s_nbh + n * NSTR + f0 + 4) = rB;
        }
    }
    __syncthreads();

    // ---- P3: score partials. thread = (n, j-quarter); tile read exactly once.
    //      acc[t] packs heads (2t, 2t+1) via p^T[j][h] broadcast reads. ----
    {
        const int n = tid & 63, jh = tid >> 6;
        const float* row = s_nbh + n * NSTR + jh * 32;
        const float* pt  = s_pt + (jh * 32) * 8;
        u64 acc[4] = {0ull, 0ull, 0ull, 0ull};
        #pragma unroll 4
        for (int j = 0; j < 32; j += 4) {
            float4 v = *(const float4*)(row + j);
            #pragma unroll
            for (int s = 0; s < 4; ++s) {
                float vv = (s == 0) ? v.x : (s == 1) ? v.y : (s == 2) ? v.z : v.w;
                u64 v2 = pk2(vv, vv);
                const ulonglong2* pp = (const ulonglong2*)(pt + (j + s) * 8);
                ulonglong2 p0 = pp[0], p1 = pp[1];
                fma2(acc[0], v2, p0.x);
                fma2(acc[1], v2, p0.y);
                fma2(acc[2], v2, p1.x);
                fma2(acc[3], v2, p1.y);
            }
        }
        u64* red = (u64*)s_un;
        #pragma unroll
        for (int t = 0; t < 4; ++t)
            red[(jh * 4 + t) * 66 + n] = acc[t];
    }
    __syncthreads();

    // ---- P3r: combine quarters, mask, scale -> s_sc[h][n] ----
    {
        const int n = tid >> 2, hp = tid & 3;
        const u64* red = (const u64*)s_un;
        u64 s0 = add2_(red[(0 * 4 + hp) * 66 + n], red[(1 * 4 + hp) * 66 + n]);
        u64 s1 = add2_(red[(2 * 4 + hp) * 66 + n], red[(3 * 4 + hp) * 66 + n]);
        float2 p = upk2(add2_(s0, s1));
        const bool m = (s_mk[n] != 0);
        s_sc[(2 * hp) * 64 + n]     = m ? p.x * 0.25f : -1e9f;
        s_sc[(2 * hp + 1) * 64 + n] = m ? p.y * 0.25f : -1e9f;
    }
    __syncthreads();

    // ---- P4: softmax, one warp per head; write attn TRANSPOSED [n][h] ----
    {
        const int h = tid >> 5, lane = tid & 31;
        const float* sc = s_sc + h * 64;
        float v0 = sc[lane], v1 = sc[lane + 32];
        float mx = fmaxf(v0, v1);
        #pragma unroll
        for (int o = 16; o > 0; o >>= 1)
            mx = fmaxf(mx, __shfl_xor_sync(0xffffffffu, mx, o));
        float e0 = __expf(v0 - mx), e1 = __expf(v1 - mx);
        float s = e0 + e1;
        #pragma unroll
        for (int o = 16; o > 0; o >>= 1)
            s += __shfl_xor_sync(0xffffffffu, s, o);
        float inv = 1.0f / s;
        s_scT[lane * 8 + h]        = e0 * inv;
        s_scT[(lane + 32) * 8 + h] = e1 * inv;
    }
    __syncthreads();

    // ---- P5: u[h][j] = sum_n attn[n][h]*nbh[n][j], column-owned ----
    {
        const int w = tid >> 5, lane = tid & 31;
        const int half = lane >> 4, cc = lane & 15;
        const int col = w * 16 + cc;
        const int nbase = half * 32;
        u64 acc[4] = {0ull, 0ull, 0ull, 0ull};
        #pragma unroll 4
        for (int i = 0; i < 32; ++i) {
            const int n = nbase + i;
            float v = s_nbh[n * NSTR + col];
            u64 v2 = pk2(v, v);
            ulonglong2 a0 = *(const ulonglong2*)(s_scT + n * 8);
            ulonglong2 a1 = *(const ulonglong2*)(s_scT + n * 8 + 4);
            fma2(acc[0], v2, a0.x);
            fma2(acc[1], v2, a0.y);
            fma2(acc[2], v2, a1.x);
            fma2(acc[3], v2, a1.y);
        }
        #pragma unroll
        for (int t = 0; t < 4; ++t) {
            float2 p = upk2(acc[t]);
            p.x += __shfl_xor_sync(0xffffffffu, p.x, 16);
            p.y += __shfl_xor_sync(0xffffffffu, p.y, 16);
            if (half == 0) {
                s_u[(2 * t) * USTR + col]     = p.x;
                s_u[(2 * t + 1) * USTR + col] = p.y;
            }
        }
    }
    __syncthreads();

    // ---- P6: msg[f] = sum_j u[h(f)][j]*Wv[j][f]  (split-K, 256 threads) ----
    {
        const int c = tid & 127, half = tid >> 7;
        const int h = c >> 4;
        const float* u  = s_u + h * USTR + half * 64;
        const float* wv = Wv + (size_t)(half * 64) * FD + c;
        float a0 = 0.f, a1 = 0.f;
        #pragma unroll 8
        for (int j = 0; j < 64; j += 2) {
            a0 += u[j]     * wv[j * FD];
            a1 += u[j + 1] * wv[(j + 1) * FD];
        }
        s_part[tid] = a0 + a1;
    }
    __syncthreads();
    if (tid < 128) s_m[tid] = s_part[tid] + s_part[tid + 128];
    __syncthreads();

    // ---- P7: out[f] = x[f] + bo[f] + sum_j msg[j]*Wo[j][f]  (split-K) ----
    {
        const int c = tid & 127, half = tid >> 7;
        const float* mm = s_m + half * 64;
        const float* wo = Wo + (size_t)(half * 64) * FD + c;
        float a0 = half ? 0.f : bo[c], a1 = 0.f;
        #pragma unroll 8
        for (int j = 0; j < 64; j += 2) {
            a0 += mm[j]     * wo[j * FD];
            a1 += mm[j + 1] * wo[(j + 1) * FD];
        }
        s_part[tid] = a0 + a1;
    }
    __syncthreads();
    if (tid < 128)
        out[(size_t)atom * FD + tid] = s_xa[tid] + s_part[tid] + s_part[tid + 128];
}

extern "C" void kernel_launch(void* const* d_in, const int* in_sizes, int n_in,
                              void* d_out, int out_size)
{
    // metadata order: e, x, t, r_ij, f_ij, W_filt, b_filt, Wq, Wk, Wv, Wo, bo,
    //                 neighbors, neighbor_mask     (e and t are unused)
    const float* x    = (const float*)d_in[1];
    const float* r    = (const float*)d_in[3];
    const float* fij  = (const float*)d_in[4];
    const float* Wf   = (const float*)d_in[5];
    const float* bf   = (const float*)d_in[6];
    const float* Wq   = (const float*)d_in[7];
    const float* Wk   = (const float*)d_in[8];
    const float* Wv   = (const float*)d_in[9];
    const float* Wo   = (const float*)d_in[10];
    const float* bo   = (const float*)d_in[11];
    const int*   nbr  = (const int*)d_in[12];
    const void*  mk   = d_in[13];

    detect_mask_kernel<<<1, 256>>>((const unsigned char*)mk);
    tdt_kernel<<<BB * AA, 256>>>(x, r, fij, Wf, bf, Wq, Wk, Wv, Wo, bo,
                                 nbr, mk, (float*)d_out);
}

// round 10
// speedup vs baseline: 2.0753x; 1.0429x over previous
#include <cuda_runtime.h>
#include <math.h>

// Problem constants
#define BB    8
#define AA    512
#define NBH   64
#define FD    128
#define GD    50
// padded shared strides
#define NSTR  132   // s_nbh row stride
#define USTR  136   // u row stride
#define FSTR  52    // s_fij row stride
#define WSTR  402   // s_wf f-block stride (402 mod 32 = 18 -> 16 distinct banks)
// s_un float offsets
#define U_A0   0        // u atom0 [0,1088)
#define U_A1   1088     // u atom1 [1088,2176)
#define FIJ_O  1088     // fij current atom [1088,4416)
#define RED_O  1088     // P3 red (u64 view) [1088,3200)
#define PRT_O  2176     // P6/P7 partials [2176,2688)
#define MSG_O  2688     // msg [2688,2944)

typedef unsigned long long u64;

__device__ __forceinline__ void fma2(u64 &d, u64 a, u64 b) {
    asm("fma.rn.f32x2 %0, %1, %2, %0;" : "+l"(d) : "l"(a), "l"(b));
}
__device__ __forceinline__ u64 pk2(float lo, float hi) {
    u64 r; asm("mov.b64 %0, {%1, %2};" : "=l"(r) : "f"(lo), "f"(hi)); return r;
}
__device__ __forceinline__ float2 upk2(u64 v) {
    float2 t; asm("mov.b64 {%0, %1}, %2;" : "=f"(t.x), "=f"(t.y) : "l"(v)); return t;
}
__device__ __forceinline__ u64 mul2_(u64 a, u64 b) {
    u64 r; asm("mul.rn.f32x2 %0, %1, %2;" : "=l"(r) : "l"(a), "l"(b)); return r;
}
__device__ __forceinline__ u64 add2_(u64 a, u64 b) {
    u64 r; asm("add.rn.f32x2 %0, %1, %2;" : "=l"(r) : "l"(a), "l"(b)); return r;
}

__device__ int g_mask_u8;

// Detect 1-byte bool vs 4-byte int mask (deterministic).
__global__ void detect_mask_kernel(const unsigned char* __restrict__ m) {
    __shared__ int found;
    if (threadIdx.x == 0) found = 0;
    __syncthreads();
    int acc = 0;
    for (int i = threadIdx.x * 4 + 1; i < 8192; i += blockDim.x * 4)
        if (m[i]) acc = 1;
    if (acc) atomicOr(&found, 1);
    __syncthreads();
    if (threadIdx.x == 0) g_mask_u8 = found;
}

__global__ __launch_bounds__(256, 3)
void tdt_kernel(const float* __restrict__ x,
                const float* __restrict__ r_ij,
                const float* __restrict__ f_ij,
                const float* __restrict__ Wf,
                const float* __restrict__ bfilt,
                const float* __restrict__ Wq,
                const float* __restrict__ Wk,
                const float* __restrict__ Wv,
                const float* __restrict__ Wo,
                const float* __restrict__ bo,
                const int*   __restrict__ nbr,
                const void*  __restrict__ maskp,
                float*       __restrict__ out)
{
    __shared__ __align__(16) float s_nbh[NBH * NSTR];   // 33.8 KB (epoch: s_wf)
    __shared__ __align__(16) float s_pt[2112];          // p^T per atom a*1056; sc/scT overlay
    __shared__ __align__(16) float s_un[4416];          // u / fij / red / partials / msg
    __shared__ __align__(16) float s_q[2 * FD];
    __shared__ __align__(16) float s_xa[2 * FD];
    __shared__ float s_C[2 * NBH];
    __shared__ int   s_nb[2 * NBH];
    __shared__ int   s_mk[2 * NBH];

    float* const s_wf = s_nbh;

    const int tid   = threadIdx.x;
    const int atom0 = blockIdx.x * 2;                  // pair never crosses batch (512 even)
    const int b     = atom0 >> 9;
    const float* xb = x + (size_t)b * (AA * FD);
    const size_t an = (size_t)atom0 * NBH;             // 128 n-slots for the pair
    const int u8 = g_mask_u8;

    // ---- P0: stage Wf (float2 — WSTR*4 is 8B- but not 16B-aligned), fij_a0, x pair ----
    {
        const float2* wsrc = (const float2*)Wf;        // 3200 float2
        for (int i = tid; i < 3200; i += 256) {
            int g = i >> 6, rem = i & 63;              // rem = ftb*4 + k2
            int ftb = rem >> 2, k2 = rem & 3;
            *(float2*)(s_wf + ftb * WSTR + g * 8 + k2 * 2) = wsrc[i];
        }
    }
    {
        const float2* fsrc = (const float2*)(f_ij + an * GD);
        for (int i = tid; i < 1600; i += 256) {
            int r = i / 25, c2 = i - r * 25;
            *(float2*)(s_un + FIJ_O + r * FSTR + c2 * 2) = fsrc[i];
        }
    }
    s_xa[tid] = x[(size_t)atom0 * FD + tid];
    if (tid < 128) {
        float r = r_ij[an + tid];
        s_C[tid]  = (r < 5.0f) ? 0.5f * (cospif(r * 0.2f) + 1.0f) : 0.0f;
        s_nb[tid] = nbr[an + tid];
        int mv;
        if (u8) mv = ((const unsigned char*)maskp)[an + tid];
        else    mv = ((const int*)maskp)[an + tid];
        s_mk[tid] = (mv != 0);
    }
    __syncthreads();

    // ---- P1: q = x @ Wq for BOTH atoms, one Wq pass (split-K) ----
    {
        const int c = tid & 127, half = tid >> 7;
        const float* wq  = Wq + (size_t)(half * 64) * FD + c;
        const float* xs0 = s_xa + half * 64;
        const float* xs1 = s_xa + 128 + half * 64;
        float a00 = 0.f, a01 = 0.f, a10 = 0.f, a11 = 0.f;
        #pragma unroll 8
        for (int j = 0; j < 64; j += 2) {
            float w0 = wq[j * FD], w1 = wq[(j + 1) * FD];
            a00 += xs0[j] * w0;  a01 += xs0[j + 1] * w1;
            a10 += xs1[j] * w0;  a11 += xs1[j + 1] * w1;
        }
        s_un[tid]       = a00 + a01;
        s_un[256 + tid] = a10 + a11;
    }
    __syncthreads();
    {
        const int aa = tid >> 7, c = tid & 127;
        s_q[aa * 128 + c] = s_un[aa * 256 + c] + s_un[aa * 256 + c + 128];
    }
    __syncthreads();

    // ---- P2a: p^T[j][h] for BOTH atoms, one Wk pass (coalesced rows) ----
    {
        const int w = tid >> 5, k = tid & 31, h = k >> 2;
        const float4 qc0 = *(const float4*)(s_q + 4 * k);
        const float4 qc1 = *(const float4*)(s_q + 128 + 4 * k);
        #pragma unroll 4
        for (int jj = 0; jj < 16; ++jj) {
            const int j = w * 16 + jj;
            float4 wv = *(const float4*)(Wk + j * FD + 4 * k);
            float d0 = wv.x * qc0.x + wv.y * qc0.y + wv.z * qc0.z + wv.w * qc0.w;
            float d1 = wv.x * qc1.x + wv.y * qc1.y + wv.z * qc1.z + wv.w * qc1.w;
            d0 += __shfl_xor_sync(0xffffffffu, d0, 1);
            d0 += __shfl_xor_sync(0xffffffffu, d0, 2);
            d1 += __shfl_xor_sync(0xffffffffu, d1, 1);
            d1 += __shfl_xor_sync(0xffffffffu, d1, 2);
            if ((k & 3) == 0) {
                s_pt[j * 8 + h]        = d0;
                s_pt[1056 + j * 8 + h] = d1;
            }
        }
    }

    // ================= per-atom loop =================
    for (int a = 0; a < 2; ++a) {
        if (a == 1) {
            // s_nbh free after P5_a0 sync: restage Wf + fij_a1
            const float2* wsrc = (const float2*)Wf;
            for (int i = tid; i < 3200; i += 256) {
                int g = i >> 6, rem = i & 63;
                int ftb = rem >> 2, k2 = rem & 3;
                *(float2*)(s_wf + ftb * WSTR + g * 8 + k2 * 2) = wsrc[i];
            }
            const float2* fsrc = (const float2*)(f_ij + (an + NBH) * GD);
            for (int i = tid; i < 1600; i += 256) {
                int r = i / 25, c2 = i - r * 25;
                *(float2*)(s_un + FIJ_O + r * FSTR + c2 * 2) = fsrc[i];
            }
            __syncthreads();
        }

        // ---- P2b: filter GEMM + cutoff + gather -> s_nbh ----
        {
            const int ft = tid & 15, nt = tid >> 4;
            const int f0 = ft * 8, n0 = nt * 4;
            u64 acc[4][4];
            {
                ulonglong2 bA = *(const ulonglong2*)(bfilt + f0);
                ulonglong2 bB = *(const ulonglong2*)(bfilt + f0 + 4);
                #pragma unroll
                for (int i = 0; i < 4; ++i) {
                    acc[i][0] = bA.x; acc[i][1] = bA.y;
                    acc[i][2] = bB.x; acc[i][3] = bB.y;
                }
            }
            const float* fr = s_un + FIJ_O + n0 * FSTR;
            const float* wbase = s_wf + ft * WSTR;
            for (int g = 0; g < GD; g += 2) {
                u64 av[4];
                #pragma unroll
                for (int i = 0; i < 4; ++i) av[i] = *(const u64*)(fr + i * FSTR + g);
                #pragma unroll
                for (int s = 0; s < 2; ++s) {
                    const u64* wr = (const u64*)(wbase + (g + s) * 8);
                    u64 w0 = wr[0], w1 = wr[1], w2 = wr[2], w3 = wr[3];
                    #pragma unroll
                    for (int i = 0; i < 4; ++i) {
                        float2 t = upk2(av[i]);
                        float aval = s ? t.y : t.x;
                        u64 a2 = pk2(aval, aval);
                        fma2(acc[i][0], a2, w0);
                        fma2(acc[i][1], a2, w1);
                        fma2(acc[i][2], a2, w2);
                        fma2(acc[i][3], a2, w3);
                    }
                }
            }
            __syncthreads();   // all s_wf reads done before s_nbh stores (alias)
            #pragma unroll
            for (int i = 0; i < 4; ++i) {
                const int n = n0 + i;
                const float c = s_C[a * NBH + n];
                const u64 c2 = pk2(c, c);
                const float* xg = xb + (size_t)s_nb[a * NBH + n] * FD + f0;
                ulonglong2 gA = *(const ulonglong2*)(xg);
                ulonglong2 gB = *(const ulonglong2*)(xg + 4);
                ulonglong2 rA, rB;
                rA.x = mul2_(mul2_(acc[i][0], gA.x), c2);
                rA.y = mul2_(mul2_(acc[i][1], gA.y), c2);
                rB.x = mul2_(mul2_(acc[i][2], gB.x), c2);
                rB.y = mul2_(mul2_(acc[i][3], gB.y), c2);
                *(ulonglong2*)(s_nbh + n * NSTR + f0)     = rA;
                *(ulonglong2*)(s_nbh + n * NSTR + f0 + 4) = rB;
            }
        }
        __syncthreads();

        // ---- P3: score partials, tile read once ----
        {
            const int n = tid & 63, jh = tid >> 6;
            const float* row = s_nbh + n * NSTR + jh * 32;
            const float* pt  = s_pt + a * 1056 + (jh * 32) * 8;
            u64 acc[4] = {0ull, 0ull, 0ull, 0ull};
            #pragma unroll 4
            for (int j = 0; j < 32; j += 4) {
                float4 v = *(const float4*)(row + j);
                #pragma unroll
                for (int s = 0; s < 4; ++s) {
                    float vv = (s == 0) ? v.x : (s == 1) ? v.y : (s == 2) ? v.z : v.w;
                    u64 v2 = pk2(vv, vv);
                    const ulonglong2* pp = (const ulonglong2*)(pt + (j + s) * 8);
                    ulonglong2 p0 = pp[0], p1 = pp[1];
                    fma2(acc[0], v2, p0.x);
                    fma2(acc[1], v2, p0.y);
                    fma2(acc[2], v2, p1.x);
                    fma2(acc[3], v2, p1.y);
                }
            }
            u64* red = (u64*)(s_un + RED_O);
            #pragma unroll
            for (int t = 0; t < 4; ++t)
                red[(jh * 4 + t) * 66 + n] = acc[t];
        }
        __syncthreads();

        // ---- P3r: combine quarters, mask, scale -> sc[h][n] (overlay p_a) ----
        {
            const int n = tid >> 2, hp = tid & 3;
            const u64* red = (const u64*)(s_un + RED_O);
            u64 s0 = add2_(red[(0 * 4 + hp) * 66 + n], red[(1 * 4 + hp) * 66 + n]);
            u64 s1 = add2_(red[(2 * 4 + hp) * 66 + n], red[(3 * 4 + hp) * 66 + n]);
            float2 p = upk2(add2_(s0, s1));
            const bool m = (s_mk[a * NBH + n] != 0);
            float* sc = s_pt + a * 1056;
            sc[(2 * hp) * 64 + n]     = m ? p.x * 0.25f : -1e9f;
            sc[(2 * hp + 1) * 64 + n] = m ? p.y * 0.25f : -1e9f;
        }
        __syncthreads();

        // ---- P4: softmax, one warp per head; attn transposed [n][h] ----
        {
            const int h = tid >> 5, lane = tid & 31;
            const float* sc = s_pt + a * 1056 + h * 64;
            float* scT = s_pt + a * 1056 + 512;
            float v0 = sc[lane], v1 = sc[lane + 32];
            float mx = fmaxf(v0, v1);
            #pragma unroll
            for (int o = 16; o > 0; o >>= 1)
                mx = fmaxf(mx, __shfl_xor_sync(0xffffffffu, mx, o));
            float e0 = __expf(v0 - mx), e1 = __expf(v1 - mx);
            float s = e0 + e1;
            #pragma unroll
            for (int o = 16; o > 0; o >>= 1)
                s += __shfl_xor_sync(0xffffffffu, s, o);
            float inv = 1.0f / s;
            scT[lane * 8 + h]        = e0 * inv;
            scT[(lane + 32) * 8 + h] = e1 * inv;
        }
        __syncthreads();

        // ---- P5: u[h][j], column-owned, tile read once ----
        {
            const int w = tid >> 5, lane = tid & 31;
            const int half = lane >> 4, cc = lane & 15;
            const int col = w * 16 + cc;
            const int nbase = half * 32;
            const float* scT = s_pt + a * 1056 + 512;
            float* su = s_un + a * 1088;
            u64 acc[4] = {0ull, 0ull, 0ull, 0ull};
            #pragma unroll 4
            for (int i = 0; i < 32; ++i) {
                const int n = nbase + i;
                float v = s_nbh[n * NSTR + col];
                u64 v2 = pk2(v, v);
                ulonglong2 a0 = *(const ulonglong2*)(scT + n * 8);
                ulonglong2 a1 = *(const ulonglong2*)(scT + n * 8 + 4);
                fma2(acc[0], v2, a0.x);
                fma2(acc[1], v2, a0.y);
                fma2(acc[2], v2, a1.x);
                fma2(acc[3], v2, a1.y);
            }
            #pragma unroll
            for (int t = 0; t < 4; ++t) {
                float2 p = upk2(acc[t]);
                p.x += __shfl_xor_sync(0xffffffffu, p.x, 16);
                p.y += __shfl_xor_sync(0xffffffffu, p.y, 16);
                if (half == 0) {
                    su[(2 * t) * USTR + col]     = p.x;
                    su[(2 * t + 1) * USTR + col] = p.y;
                }
            }
        }
        __syncthreads();
    }

    // ---- P6: msg for BOTH atoms, one Wv pass (split-K) ----
    {
        const int c = tid & 127, half = tid >> 7, h = c >> 4;
        const float* wv = Wv + (size_t)(half * 64) * FD + c;
        const float* u0 = s_un + U_A0 + h * USTR + half * 64;
        const float* u1 = s_un + U_A1 + h * USTR + half * 64;
        float p00 = 0.f, p01 = 0.f, p10 = 0.f, p11 = 0.f;
        #pragma unroll 8
        for (int j = 0; j < 64; j += 2) {
            float w0 = wv[j * FD], w1 = wv[(j + 1) * FD];
            p00 += u0[j] * w0;  p01 += u0[j + 1] * w1;
            p10 += u1[j] * w0;  p11 += u1[j + 1] * w1;
        }
        s_un[PRT_O + tid]       = p00 + p01;
        s_un[PRT_O + 256 + tid] = p10 + p11;
    }
    __syncthreads();
    {
        const int aa = tid >> 7, c = tid & 127;
        s_un[MSG_O + aa * 128 + c] =
            s_un[PRT_O + aa * 256 + c] + s_un[PRT_O + aa * 256 + c + 128];
    }
    __syncthreads();

    // ---- P7: out for BOTH atoms, one Wo pass (split-K) ----
    {
        const int c = tid & 127, half = tid >> 7;
        const float* wo = Wo + (size_t)(half * 64) * FD + c;
        const float* m0 = s_un + MSG_O + half * 64;
        const float* m1 = s_un + MSG_O + 128 + half * 64;
        float bb = half ? 0.f : bo[c];
        float p00 = bb, p01 = 0.f, p10 = bb, p11 = 0.f;
        #pragma unroll 8
        for (int j = 0; j < 64; j += 2) {
            float w0 = wo[j * FD], w1 = wo[(j + 1) * FD];
            p00 += m0[j] * w0;  p01 += m0[j + 1] * w1;
            p10 += m1[j] * w0;  p11 += m1[j + 1] * w1;
        }
        __syncthreads();   // clean epoch before PRT overwrite
        s_un[PRT_O + tid]       = p00 + p01;
        s_un[PRT_O + 256 + tid] = p10 + p11;
    }
    __syncthreads();
    {
        const int aa = tid >> 7, c = tid & 127;
        out[(size_t)atom0 * FD + tid] =
            s_xa[tid] + s_un[PRT_O + aa * 256 + c] + s_un[PRT_O + aa * 256 + c + 128];
    }
}

extern "C" void kernel_launch(void* const* d_in, const int* in_sizes, int n_in,
                              void* d_out, int out_size)
{
    // metadata order: e, x, t, r_ij, f_ij, W_filt, b_filt, Wq, Wk, Wv, Wo, bo,
    //                 neighbors, neighbor_mask     (e and t are unused)
    const float* x    = (const float*)d_in[1];
    const float* r    = (const float*)d_in[3];
    const float* fij  = (const float*)d_in[4];
    const float* Wf   = (const float*)d_in[5];
    const float* bf   = (const float*)d_in[6];
    const float* Wq   = (const float*)d_in[7];
    const float* Wk   = (const float*)d_in[8];
    const float* Wv   = (const float*)d_in[9];
    const float* Wo   = (const float*)d_in[10];
    const float* bo   = (const float*)d_in[11];
    const int*   nbr  = (const int*)d_in[12];
    const void*  mk   = d_in[13];

    detect_mask_kernel<<<1, 256>>>((const unsigned char*)mk);
    tdt_kernel<<<BB * AA / 2, 256>>>(x, r, fij, Wf, bf, Wq, Wk, Wv, Wo, bo,
                                     nbr, mk, (float*)d_out);
}

// round 12
// speedup vs baseline: 2.2070x; 1.0635x over previous
#include <cuda_runtime.h>
#include <math.h>

// Problem constants
#define BB    8
#define AA    512
#define NBH   64
#define FD    128
#define GD    50
// padded shared strides
#define NSTR  132   // s_nbh row stride
#define USTR  136   // u row stride
#define FSTR  52    // s_fij row stride
#define WSTR  404   // s_wf f-block stride (404*4B = 16B-aligned; ft*20 mod 32 -> phase-conflict-free LDS.128)
// s_un float offsets
#define U_A0   0        // u atom0 [0,1088)  (also P1 partials [0,1024) before P5 a=0)
#define U_A1   1088     // u atom1 [1088,2176)
#define FIJ_O  1088     // fij current atom [1088,4416)
#define RED_O  1088     // P3 red (u64 view) [1088,3200)
#define P6P_O  2176     // P6/P7 partials [2176,3200) (u64[512])
#define MSG_O  3200     // msg [3200,3456)

typedef unsigned long long u64;

__device__ __forceinline__ void fma2(u64 &d, u64 a, u64 b) {
    asm("fma.rn.f32x2 %0, %1, %2, %0;" : "+l"(d) : "l"(a), "l"(b));
}
__device__ __forceinline__ u64 pk2(float lo, float hi) {
    u64 r; asm("mov.b64 %0, {%1, %2};" : "=l"(r) : "f"(lo), "f"(hi)); return r;
}
__device__ __forceinline__ float2 upk2(u64 v) {
    float2 t; asm("mov.b64 {%0, %1}, %2;" : "=f"(t.x), "=f"(t.y) : "l"(v)); return t;
}
__device__ __forceinline__ u64 mul2_(u64 a, u64 b) {
    u64 r; asm("mul.rn.f32x2 %0, %1, %2;" : "=l"(r) : "l"(a), "l"(b)); return r;
}
__device__ __forceinline__ u64 add2_(u64 a, u64 b) {
    u64 r; asm("add.rn.f32x2 %0, %1, %2;" : "=l"(r) : "l"(a), "l"(b)); return r;
}

__device__ int g_mask_u8;

// Detect 1-byte bool vs 4-byte int mask (deterministic).
__global__ void detect_mask_kernel(const unsigned char* __restrict__ m) {
    __shared__ int found;
    if (threadIdx.x == 0) found = 0;
    __syncthreads();
    int acc = 0;
    for (int i = threadIdx.x * 4 + 1; i < 8192; i += blockDim.x * 4)
        if (m[i]) acc = 1;
    if (acc) atomicOr(&found, 1);
    __syncthreads();
    if (threadIdx.x == 0) g_mask_u8 = found;
}

__global__ __launch_bounds__(256, 3)
void tdt_kernel(const float* __restrict__ x,
                const float* __restrict__ r_ij,
                const float* __restrict__ f_ij,
                const float* __restrict__ Wf,
                const float* __restrict__ bfilt,
                const float* __restrict__ Wq,
                const float* __restrict__ Wk,
                const float* __restrict__ Wv,
                const float* __restrict__ Wo,
                const float* __restrict__ bo,
                const int*   __restrict__ nbr,
                const void*  __restrict__ maskp,
                float*       __restrict__ out)
{
    __shared__ __align__(16) float s_nbh[NBH * NSTR];   // 33.8 KB (epoch: s_wf, needs 6460f)
    __shared__ __align__(16) float s_pt[2112];          // p^T per atom a*1056; sc/scT overlay
    __shared__ __align__(16) float s_un[4416];          // u / fij / red / partials / msg
    __shared__ __align__(16) float s_q[2 * FD];
    __shared__ __align__(16) float s_xa[2 * FD];
    __shared__ float s_C[2 * NBH];
    __shared__ int   s_nb[2 * NBH];
    __shared__ int   s_mk[2 * NBH];

    float* const s_wf = s_nbh;

    const int tid   = threadIdx.x;
    const int atom0 = blockIdx.x * 2;                  // pair never crosses batch (512 even)
    const int b     = atom0 >> 9;
    const float* xb = x + (size_t)b * (AA * FD);
    const size_t an = (size_t)atom0 * NBH;             // 128 n-slots for the pair
    const int u8 = g_mask_u8;

    // ---- P0: stage Wf (float4 -> WSTR=404 is 16B aligned), fij_a0, x pair ----
    {
        const float4* wsrc = (const float4*)Wf;        // 1600 float4
        for (int i = tid; i < 1600; i += 256) {
            int g = i >> 5, rem = i & 31;              // rem = ftb*2 + k4
            int ftb = rem >> 1, k4 = rem & 1;
            *(float4*)(s_wf + ftb * WSTR + g * 8 + k4 * 4) = wsrc[i];
        }
    }
    {
        const float2* fsrc = (const float2*)(f_ij + an * GD);
        for (int i = tid; i < 1600; i += 256) {
            int r = i / 25, c2 = i - r * 25;
            *(float2*)(s_un + FIJ_O + r * FSTR + c2 * 2) = fsrc[i];
        }
    }
    s_xa[tid] = x[(size_t)atom0 * FD + tid];
    if (tid < 128) {
        float r = r_ij[an + tid];
        s_C[tid]  = (r < 5.0f) ? 0.5f * (cospif(r * 0.2f) + 1.0f) : 0.0f;
        s_nb[tid] = nbr[an + tid];
        int mv;
        if (u8) mv = ((const unsigned char*)maskp)[an + tid];
        else    mv = ((const int*)maskp)[an + tid];
        s_mk[tid] = (mv != 0);
    }
    __syncthreads();

    // ---- P1: q = x @ Wq, BOTH atoms; u64 c-pair loads, 4-way k-split ----
    {
        const int cg = tid & 63, q = tid >> 6;         // c = 2*cg, j in [q*32, q*32+32)
        const float* wq  = Wq + (size_t)(q * 32) * FD + 2 * cg;
        const float* xj0 = s_xa + q * 32;
        const float* xj1 = s_xa + 128 + q * 32;
        u64 a0 = 0ull, a1 = 0ull;
        #pragma unroll 8
        for (int j = 0; j < 32; ++j) {
            u64 w = *(const u64*)(wq + j * FD);
            float v0 = xj0[j], v1 = xj1[j];
            fma2(a0, pk2(v0, v0), w);
            fma2(a1, pk2(v1, v1), w);
        }
        u64* part = (u64*)(s_un + U_A0);
        part[q * 64 + cg]       = a0;
        part[256 + q * 64 + cg] = a1;
    }
    __syncthreads();
    if (tid < 128) {
        const int a = tid >> 6, cg = tid & 63;
        const u64* part = (const u64*)(s_un + U_A0) + a * 256;
        u64 s = add2_(add2_(part[cg], part[64 + cg]),
                      add2_(part[128 + cg], part[192 + cg]));
        *(u64*)(s_q + a * 128 + 2 * cg) = s;
    }
    __syncthreads();

    // ---- P2a: p^T[j][h] for BOTH atoms, one Wk pass (coalesced rows) ----
    {
        const int w = tid >> 5, k = tid & 31, h = k >> 2;
        const float4 qc0 = *(const float4*)(s_q + 4 * k);
        const float4 qc1 = *(const float4*)(s_q + 128 + 4 * k);
        #pragma unroll 4
        for (int jj = 0; jj < 16; ++jj) {
            const int j = w * 16 + jj;
            float4 wv = *(const float4*)(Wk + j * FD + 4 * k);
            float d0 = wv.x * qc0.x + wv.y * qc0.y + wv.z * qc0.z + wv.w * qc0.w;
            float d1 = wv.x * qc1.x + wv.y * qc1.y + wv.z * qc1.z + wv.w * qc1.w;
            d0 += __shfl_xor_sync(0xffffffffu, d0, 1);
            d0 += __shfl_xor_sync(0xffffffffu, d0, 2);
            d1 += __shfl_xor_sync(0xffffffffu, d1, 1);
            d1 += __shfl_xor_sync(0xffffffffu, d1, 2);
            if ((k & 3) == 0) {
                s_pt[j * 8 + h]        = d0;
                s_pt[1056 + j * 8 + h] = d1;
            }
        }
    }

    // ================= per-atom loop =================
    for (int a = 0; a < 2; ++a) {
        if (a == 1) {
            // s_nbh free after P5_a0 sync: restage Wf + fij_a1
            const float4* wsrc = (const float4*)Wf;
            for (int i = tid; i < 1600; i += 256) {
                int g = i >> 5, rem = i & 31;
                int ftb = rem >> 1, k4 = rem & 1;
                *(float4*)(s_wf + ftb * WSTR + g * 8 + k4 * 4) = wsrc[i];
            }
            const float2* fsrc = (const float2*)(f_ij + (an + NBH) * GD);
            for (int i = tid; i < 1600; i += 256) {
                int r = i / 25, c2 = i - r * 25;
                *(float2*)(s_un + FIJ_O + r * FSTR + c2 * 2) = fsrc[i];
            }
            __syncthreads();
        }

        // ---- P2b: filter GEMM + cutoff + gather -> s_nbh (wide LDS) ----
        {
            const int ft = tid & 15, nt = tid >> 4;
            const int f0 = ft * 8, n0 = nt * 4;
            u64 acc[4][4];
            {
                ulonglong2 bA = *(const ulonglong2*)(bfilt + f0);
                ulonglong2 bB = *(const ulonglong2*)(bfilt + f0 + 4);
                #pragma unroll
                for (int i = 0; i < 4; ++i) {
                    acc[i][0] = bA.x; acc[i][1] = bA.y;
                    acc[i][2] = bB.x; acc[i][3] = bB.y;
                }
            }
            const float* fr = s_un + FIJ_O + n0 * FSTR;
            const float* wbase = s_wf + ft * WSTR;
            #pragma unroll 2
            for (int g = 0; g < 48; g += 4) {
                float4 a4[4];
                #pragma unroll
                for (int i = 0; i < 4; ++i)
                    a4[i] = *(const float4*)(fr + i * FSTR + g);
                #pragma unroll
                for (int s = 0; s < 4; ++s) {
                    const ulonglong2* wr = (const ulonglong2*)(wbase + (g + s) * 8);
                    ulonglong2 wA = wr[0], wB = wr[1];
                    #pragma unroll
                    for (int i = 0; i < 4; ++i) {
                        float av = (s == 0) ? a4[i].x : (s == 1) ? a4[i].y :
                                   (s == 2) ? a4[i].z : a4[i].w;
                        u64 a2 = pk2(av, av);
                        fma2(acc[i][0], a2, wA.x);
                        fma2(acc[i][1], a2, wA.y);
                        fma2(acc[i][2], a2, wB.x);
                        fma2(acc[i][3], a2, wB.y);
                    }
                }
            }
            {   // remainder g = 48, 49
                float2 ar[4];
                #pragma unroll
                for (int i = 0; i < 4; ++i)
                    ar[i] = *(const float2*)(fr + i * FSTR + 48);
                #pragma unroll
                for (int s = 0; s < 2; ++s) {
                    const ulonglong2* wr = (const ulonglong2*)(wbase + (48 + s) * 8);
                    ulonglong2 wA = wr[0], wB = wr[1];
                    #pragma unroll
                    for (int i = 0; i < 4; ++i) {
                        float av = s ? ar[i].y : ar[i].x;
                        u64 a2 = pk2(av, av);
                        fma2(acc[i][0], a2, wA.x);
                        fma2(acc[i][1], a2, wA.y);
                        fma2(acc[i][2], a2, wB.x);
                        fma2(acc[i][3], a2, wB.y);
                    }
                }
            }
            __syncthreads();   // all s_wf reads done before s_nbh stores (alias)
            #pragma unroll
            for (int i = 0; i < 4; ++i) {
                const int n = n0 + i;
                const float c = s_C[a * NBH + n];
                const u64 c2 = pk2(c, c);
                const float* xg = xb + (size_t)s_nb[a * NBH + n] * FD + f0;
                ulonglong2 gA = *(const ulonglong2*)(xg);
                ulonglong2 gB = *(const ulonglong2*)(xg + 4);
                ulonglong2 rA, rB;
                rA.x = mul2_(mul2_(acc[i][0], gA.x), c2);
                rA.y = mul2_(mul2_(acc[i][1], gA.y), c2);
                rB.x = mul2_(mul2_(acc[i][2], gB.x), c2);
                rB.y = mul2_(mul2_(acc[i][3], gB.y), c2);
                *(ulonglong2*)(s_nbh + n * NSTR + f0)     = rA;
                *(ulonglong2*)(s_nbh + n * NSTR + f0 + 4) = rB;
            }
        }
        __syncthreads();

        // ---- P3: score partials, tile read once ----
        {
            const int n = tid & 63, jh = tid >> 6;
            const float* row = s_nbh + n * NSTR + jh * 32;
            const float* pt  = s_pt + a * 1056 + (jh * 32) * 8;
            u64 acc[4] = {0ull, 0ull, 0ull, 0ull};
            #pragma unroll 4
            for (int j = 0; j < 32; j += 4) {
                float4 v = *(const float4*)(row + j);
                #pragma unroll
                for (int s = 0; s < 4; ++s) {
                    float vv = (s == 0) ? v.x : (s == 1) ? v.y : (s == 2) ? v.z : v.w;
                    u64 v2 = pk2(vv, vv);
                    const ulonglong2* pp = (const ulonglong2*)(pt + (j + s) * 8);
                    ulonglong2 p0 = pp[0], p1 = pp[1];
                    fma2(acc[0], v2, p0.x);
                    fma2(acc[1], v2, p0.y);
                    fma2(acc[2], v2, p1.x);
                    fma2(acc[3], v2, p1.y);
                }
            }
            u64* red = (u64*)(s_un + RED_O);
            #pragma unroll
            for (int t = 0; t < 4; ++t)
                red[(jh * 4 + t) * 66 + n] = acc[t];
        }
        __syncthreads();

        // ---- P3r: combine quarters, mask, scale -> sc[h][n] (overlay p_a) ----
        {
            const int n = tid >> 2, hp = tid & 3;
            const u64* red = (const u64*)(s_un + RED_O);
            u64 s0 = add2_(red[(0 * 4 + hp) * 66 + n], red[(1 * 4 + hp) * 66 + n]);
            u64 s1 = add2_(red[(2 * 4 + hp) * 66 + n], red[(3 * 4 + hp) * 66 + n]);
            float2 p = upk2(add2_(s0, s1));
            const bool m = (s_mk[a * NBH + n] != 0);
            float* sc = s_pt + a * 1056;
            sc[(2 * hp) * 64 + n]     = m ? p.x * 0.25f : -1e9f;
            sc[(2 * hp + 1) * 64 + n] = m ? p.y * 0.25f : -1e9f;
        }
        __syncthreads();

        // ---- P4: softmax, one warp per head; attn transposed [n][h] ----
        {
            const int h = tid >> 5, lane = tid & 31;
            const float* sc = s_pt + a * 1056 + h * 64;
            float* scT = s_pt + a * 1056 + 512;
            float v0 = sc[lane], v1 = sc[lane + 32];
            float mx = fmaxf(v0, v1);
            #pragma unroll
            for (int o = 16; o > 0; o >>= 1)
                mx = fmaxf(mx, __shfl_xor_sync(0xffffffffu, mx, o));
            float e0 = __expf(v0 - mx), e1 = __expf(v1 - mx);
            float s = e0 + e1;
            #pragma unroll
            for (int o = 16; o > 0; o >>= 1)
                s += __shfl_xor_sync(0xffffffffu, s, o);
            float inv = 1.0f / s;
            scT[lane * 8 + h]        = e0 * inv;
            scT[(lane + 32) * 8 + h] = e1 * inv;
        }
        __syncthreads();

        // ---- P5: u[h][j], column-owned, tile read once ----
        {
            const int w = tid >> 5, lane = tid & 31;
            const int half = lane >> 4, cc = lane & 15;
            const int col = w * 16 + cc;
            const int nbase = half * 32;
            const float* scT = s_pt + a * 1056 + 512;
            float* su = s_un + a * 1088;
            u64 acc[4] = {0ull, 0ull, 0ull, 0ull};
            #pragma unroll 4
            for (int i = 0; i < 32; ++i) {
                const int n = nbase + i;
                float v = s_nbh[n * NSTR + col];
                u64 v2 = pk2(v, v);
                ulonglong2 a0 = *(const ulonglong2*)(scT + n * 8);
                ulonglong2 a1 = *(const ulonglong2*)(scT + n * 8 + 4);
                fma2(acc[0], v2, a0.x);
                fma2(acc[1], v2, a0.y);
                fma2(acc[2], v2, a1.x);
                fma2(acc[3], v2, a1.y);
            }
            #pragma unroll
            for (int t = 0; t < 4; ++t) {
                float2 p = upk2(acc[t]);
                p.x += __shfl_xor_sync(0xffffffffu, p.x, 16);
                p.y += __shfl_xor_sync(0xffffffffu, p.y, 16);
                if (half == 0) {
                    su[(2 * t) * USTR + col]     = p.x;
                    su[(2 * t + 1) * USTR + col] = p.y;
                }
            }
        }
        __syncthreads();
    }

    // ---- P6: msg for BOTH atoms, one Wv pass (u64 c-pair, 4-way k-split) ----
    {
        const int cg = tid & 63, q = tid >> 6;
        const int h = cg >> 3;                        // c = 2cg -> h = c/16
        const float* wv = Wv + (size_t)(q * 32) * FD + 2 * cg;
        const float* u0 = s_un + U_A0 + h * USTR + q * 32;
        const float* u1 = s_un + U_A1 + h * USTR + q * 32;
        u64 a0 = 0ull, a1 = 0ull;
        #pragma unroll 8
        for (int j = 0; j < 32; ++j) {
            u64 w = *(const u64*)(wv + j * FD);
            float v0 = u0[j], v1 = u1[j];
            fma2(a0, pk2(v0, v0), w);
            fma2(a1, pk2(v1, v1), w);
        }
        u64* part = (u64*)(s_un + P6P_O);
        part[q * 64 + cg]       = a0;
        part[256 + q * 64 + cg] = a1;
    }
    __syncthreads();
    if (tid < 128) {
        const int a = tid >> 6, cg = tid & 63;
        const u64* part = (const u64*)(s_un + P6P_O) + a * 256;
        u64 s = add2_(add2_(part[cg], part[64 + cg]),
                      add2_(part[128 + cg], part[192 + cg]));
        *(u64*)(s_un + MSG_O + a * 128 + 2 * cg) = s;
    }
    __syncthreads();

    // ---- P7: out for BOTH atoms, one Wo pass ----
    {
        const int cg = tid & 63, q = tid >> 6;
        const float* wo = Wo + (size_t)(q * 32) * FD + 2 * cg;
        const float* m0 = s_un + MSG_O + q * 32;
        const float* m1 = s_un + MSG_O + 128 + q * 32;
        u64 a0 = 0ull, a1 = 0ull;
        #pragma unroll 8
        for (int j = 0; j < 32; ++j) {
            u64 w = *(const u64*)(wo + j * FD);
            float v0 = m0[j], v1 = m1[j];
            fma2(a0, pk2(v0, v0), w);
            fma2(a1, pk2(v1, v1), w);
        }
        u64* part = (u64*)(s_un + P6P_O);   // P6 partials dead (reduce barrier passed)
        part[q * 64 + cg]       = a0;
        part[256 + q * 64 + cg] = a1;
    }
    __syncthreads();
    if (tid < 128) {
        const int a = tid >> 6, cg = tid & 63;
        const u64* part = (const u64*)(s_un + P6P_O) + a * 256;
        u64 s = add2_(add2_(part[cg], part[64 + cg]),
                      add2_(part[128 + cg], part[192 + cg]));
        u64 bo2 = *(const u64*)(bo + 2 * cg);
        u64 xa2 = *(const u64*)(s_xa + a * 128 + 2 * cg);
        u64 r = add2_(add2_(s, bo2), xa2);
        *(u64*)(out + (size_t)atom0 * FD + a * 128 + 2 * cg) = r;
    }
}

extern "C" void kernel_launch(void* const* d_in, const int* in_sizes, int n_in,
                              void* d_out, int out_size)
{
    // metadata order: e, x, t, r_ij, f_ij, W_filt, b_filt, Wq, Wk, Wv, Wo, bo,
    //                 neighbors, neighbor_mask     (e and t are unused)
    const float* x    = (const float*)d_in[1];
    const float* r    = (const float*)d_in[3];
    const float* fij  = (const float*)d_in[4];
    const float* Wf   = (const float*)d_in[5];
    const float* bf   = (const float*)d_in[6];
    const float* Wq   = (const float*)d_in[7];
    const float* Wk   = (const float*)d_in[8];
    const float* Wv   = (const float*)d_in[9];
    const float* Wo   = (const float*)d_in[10];
    const float* bo   = (const float*)d_in[11];
    const int*   nbr  = (const int*)d_in[12];
    const void*  mk   = d_in[13];

    detect_mask_kernel<<<1, 256>>>((const unsigned char*)mk);
    tdt_kernel<<<BB * AA / 2, 256>>>(x, r, fij, Wf, bf, Wq, Wk, Wv, Wo, bo,
                                     nbr, mk, (float*)d_out);
}